// round 13
// baseline (speedup 1.0000x reference)
#include <cuda_runtime.h>
#include <cuda_bf16.h>
#include <cstdint>

#define ROWS_T 36864
#define SEQ    9216
#define WL     2304
#define SCALE_S (1.0f/1179648.0f)

#define PJ_S32 8704
#define PROJ_SMEM3 ((8704 + 16896)*4)
#define OU_XS3 8704
#define OUT_SMEM3 ((8704 + 8704)*4)
#define KT0 0
#define VT0 1088
#define KT1 2176
#define VT1 3264
#define K2A_SMEM (4352*4)

__device__ float g_gate[ROWS_T*128];
__device__ unsigned short g_qwh[ROWS_T*128];
__device__ unsigned short g_kwh[ROWS_T*128];
__device__ unsigned short g_vwh[ROWS_T*128];
__device__ unsigned g_wprep[49152];
__device__ unsigned g_Ppart[128*8192];
__device__ float g_ksp[128*128];
__device__ float g_vsp[128*128];
__device__ unsigned g_Mt[36*8192];
__device__ float g_ksum[36*128];
__device__ float g_vsum[36*128];
__device__ unsigned g_atth[ROWS_T*64];

__device__ __forceinline__ float siluf(float x){ return x / (1.0f + __expf(-x)); }

__device__ __forceinline__ int win_from_nat(int r){
    int b = r / SEQ; int p = r - b*SEQ;
    int y = p / 96, x = p - y*96;
    int yr = y + 72; if (yr >= 96) yr -= 96;
    int xr = x + 72; if (xr >= 96) xr -= 96;
    int wy = yr / 48, iy = yr - wy*48;
    int wx = xr / 48, ix = xr - wx*48;
    int w = wy*2 + wx;
    int j;
    if (w == 0)      j = iy*48 + ix;
    else if (w == 1){ int sx = ix >= 24; j = sx*1152 + iy*24 + (ix - sx*24); }
    else if (w == 2){ int sy = iy >= 24; j = sy*1152 + (iy - sy*24)*48 + ix; }
    else { int sy = iy >= 24, sx = ix >= 24;
           j = (sy*2+sx)*576 + (iy - sy*24)*24 + (ix - sx*24); }
    return (b*4 + w)*WL + j;
}
__device__ __forceinline__ int nat_from_reg(int batch, int wv, int wrem){
    int wy = wv >> 1, wx = wv & 1;
    int iy, ix;
    if (wv == 0){ iy = wrem/48; ix = wrem - iy*48; }
    else if (wv == 1){ int sx = wrem >= 1152; int t = wrem - sx*1152; iy = t/24; ix = sx*24 + (t - iy*24); }
    else if (wv == 2){ int sy = wrem >= 1152; int t = wrem - sy*1152; int r = t/48; iy = sy*24 + r; ix = t - r*48; }
    else { int sg = wrem/576; int t = wrem - sg*576; int sy = sg>>1, sx = sg&1;
           int r = t/24; iy = sy*24 + r; ix = sx*24 + (t - r*24); }
    int y = wy*48 + iy + 24; if (y >= 96) y -= 96;
    int x = wx*48 + ix + 24; if (x >= 96) x -= 96;
    return batch*SEQ + y*96 + x;
}

__device__ __forceinline__ uint32_t smem_u32(const void* p){
    uint32_t a;
    asm("{ .reg .u64 t; cvta.to.shared.u64 t, %1; cvt.u32.u64 %0, t; }" : "=r"(a) : "l"(p));
    return a;
}

#define MMA_BF16(c, a0,a1,a2,a3, b0,b1) \
    asm volatile("mma.sync.aligned.m16n8k16.row.col.f32.bf16.bf16.f32 " \
        "{%0,%1,%2,%3},{%4,%5,%6,%7},{%8,%9},{%0,%1,%2,%3};" \
        : "+f"((c)[0]),"+f"((c)[1]),"+f"((c)[2]),"+f"((c)[3]) \
        : "r"(a0),"r"(a1),"r"(a2),"r"(a3),"r"(b0),"r"(b1))

#define LDM_X4(b0,b1,b2,b3,addr) \
    asm volatile("ldmatrix.sync.aligned.m8n8.x4.shared.b16 {%0,%1,%2,%3}, [%4];" \
        : "=r"(b0),"=r"(b1),"=r"(b2),"=r"(b3) : "r"(addr))
#define LDM_X4T(b0,b1,b2,b3,addr) \
    asm volatile("ldmatrix.sync.aligned.m8n8.x4.trans.shared.b16 {%0,%1,%2,%3}, [%4];" \
        : "=r"(b0),"=r"(b1),"=r"(b2),"=r"(b3) : "r"(addr))

#define CP16(dst, src) \
    asm volatile("cp.async.cg.shared.global [%0], [%1], 16;" :: "r"(dst), "l"(src))
#define CP_COMMIT asm volatile("cp.async.commit_group;")
#define CP_WAIT0  asm volatile("cp.async.wait_group 0;")

#define PACK_BF2(u, x, y) do { __nv_bfloat162 _h = __floats2bfloat162_rn((x),(y)); (u) = *(unsigned*)&_h; } while(0)

// ============ K0: weight prep ============
__global__ void prep_w(const float* __restrict__ gq, const float* __restrict__ kv,
                       const float* __restrict__ o1, const float* __restrict__ o2){
    int id = blockIdx.x*256 + threadIdx.x;
    const float* W; int rem, ncols;
    if (id < 32768){ W = (id < 16384) ? gq : kv; ncols = 256; rem = id & 16383; }
    else           { W = (id < 40960) ? o1 : o2; ncols = 128; rem = id & 8191; }
    int n  = rem >> 6;
    int r  = rem & 63;
    int kk = r >> 3, c4 = (r >> 1) & 3, h = r & 1;
    int k0 = kk*16 + h*8 + 2*c4;
    __nv_bfloat162 hh = __floats2bfloat162_rn(W[k0*ncols + n], W[(k0+1)*ncols + n]);
    g_wprep[id] = *(unsigned*)&hh;
}

// ============ K1: fused LN + (gate,Q,K,V) bf16 projection ============
__global__ void __launch_bounds__(256)
proj_fused(const float* __restrict__ src, const float* __restrict__ lg, const float* __restrict__ lb,
           const float* __restrict__ b_gq, const float* __restrict__ b_kv){
    extern __shared__ unsigned smu[];
    float* S32 = (float*)(smu + PJ_S32);
    int tid = threadIdx.x, lane = tid & 31, w = tid >> 5;
    int q = lane >> 2, c4 = lane & 3;
    int wr = w >> 1, wc = w & 1;
    int mbase = blockIdx.x * 128;
    uint32_t smb = smem_u32(smu);

    const float4* Sg = ((const float4*)src) + mbase*32;
    #pragma unroll
    for (int it=0; it<16; it++){
        int idx = tid + it*256; int row = idx>>5, cq = idx&31;
        *(float4*)&S32[row*132 + cq*4] = Sg[idx];
    }
    __syncthreads();
    if (tid < 128){
        float s=0.f, s2=0.f;
        #pragma unroll
        for (int i=0;i<32;i++){
            float4 v = *(float4*)&S32[tid*132 + i*4];
            s += v.x+v.y+v.z+v.w;
            s2 += v.x*v.x+v.y*v.y+v.z*v.z+v.w*v.w;
        }
        float mean = s*(1.f/128.f);
        float var  = s2*(1.f/128.f) - mean*mean;
        float rs   = rsqrtf(var + 1e-5f);
        #pragma unroll
        for (int i=0;i<32;i++){
            float4 v = *(float4*)&S32[tid*132 + i*4];
            float4 g4 = ((const float4*)lg)[i];
            float4 b4 = ((const float4*)lb)[i];
            float x0 = (v.x-mean)*rs*g4.x + b4.x;
            float x1 = (v.y-mean)*rs*g4.y + b4.y;
            float x2 = (v.z-mean)*rs*g4.z + b4.z;
            float x3 = (v.w-mean)*rs*g4.w + b4.w;
            __nv_bfloat162 h0 = __floats2bfloat162_rn(x0, x1);
            __nv_bfloat162 h1 = __floats2bfloat162_rn(x2, x3);
            uint2 u; u.x = *(unsigned*)&h0; u.y = *(unsigned*)&h1;
            *(uint2*)&smu[tid*68 + i*2] = u;
        }
    }
    __syncthreads();

    int lrow = (lane&7) + ((lane>>3)&1)*8;
    int lcolb = ((lane>>4)&1)*16;

    for (int nt=0; nt<4; nt++){
        const unsigned* WB = g_wprep + nt*8192;
        const float* bias  = (nt<2) ? (b_gq + nt*128) : (b_kv + (nt-2)*128);

        float c[2][8][4];
        #pragma unroll
        for (int n=0;n<8;n++){
            int col = wc*64 + n*8 + 2*c4;
            float bb0 = bias[col], bb1 = bias[col+1];
            c[0][n][0]=bb0; c[0][n][1]=bb1; c[0][n][2]=bb0; c[0][n][3]=bb1;
            c[1][n][0]=bb0; c[1][n][1]=bb1; c[1][n][2]=bb0; c[1][n][3]=bb1;
        }
        #pragma unroll
        for (int kk=0;kk<8;kk++){
            unsigned a[2][4];
            #pragma unroll
            for (int mm=0;mm<2;mm++){
                int row = wr*32 + mm*16 + lrow;
                LDM_X4(a[mm][0],a[mm][1],a[mm][2],a[mm][3], smb + row*272 + kk*32 + lcolb);
            }
            #pragma unroll
            for (int n=0;n<8;n++){
                int nabs = wc*64 + n*8 + q;
                uint2 bb = *(const uint2*)(WB + nabs*64 + kk*8 + c4*2);
                MMA_BF16(c[0][n], a[0][0],a[0][1],a[0][2],a[0][3], bb.x, bb.y);
                MMA_BF16(c[1][n], a[1][0],a[1][1],a[1][2],a[1][3], bb.x, bb.y);
            }
        }

        if (nt == 0){
            // stage silu(gate) in fragment layout -> smem fp32, then coalesced store
            #pragma unroll
            for (int mm=0;mm<2;mm++){
                int r1 = wr*32 + q + mm*16;
                #pragma unroll
                for (int n=0;n<8;n++){
                    int col = wc*64 + n*8 + 2*c4;
                    float2 y0 = { siluf(c[mm][n][0]), siluf(c[mm][n][1]) };
                    float2 y1 = { siluf(c[mm][n][2]), siluf(c[mm][n][3]) };
                    *(float2*)&S32[r1*132 + col]     = y0;
                    *(float2*)&S32[(r1+8)*132 + col] = y1;
                }
            }
            __syncthreads();
            #pragma unroll
            for (int it=0; it<16; it++){
                int idx = tid + it*256; int row = idx>>5, cq = idx&31;
                ((float4*)g_gate)[(size_t)(mbase+row)*32 + cq] = *(float4*)&S32[row*132 + cq*4];
            }
        } else {
            unsigned short* oh = (nt==1) ? g_qwh : (nt==2 ? g_kwh : g_vwh);
            #pragma unroll
            for (int mm=0;mm<2;mm++){
                int r1 = mbase + wr*32 + q + mm*16;
                int dr1 = win_from_nat(r1);
                int dr2 = win_from_nat(r1+8);
                #pragma unroll
                for (int n=0;n<8;n++){
                    int col = wc*64 + n*8 + 2*c4;
                    __nv_bfloat162 h0 = __floats2bfloat162_rn(siluf(c[mm][n][0]), siluf(c[mm][n][1]));
                    __nv_bfloat162 h1 = __floats2bfloat162_rn(siluf(c[mm][n][2]), siluf(c[mm][n][3]));
                    *(__nv_bfloat162*)(oh + dr1*128 + col) = h0;
                    *(__nv_bfloat162*)(oh + dr2*128 + col) = h1;
                }
            }
        }
    }
}

// ============ K2a: per-chunk partial P[d2][d1] (bf16 partial store) ============
__global__ void __launch_bounds__(256)
k2a_mt(){
    extern __shared__ unsigned smw[];
    int tid = threadIdx.x, lane = tid & 31, w = tid >> 5;
    int q = lane >> 2, c4 = lane & 3;
    int cid = blockIdx.x;
    int batch = cid >> 5, r = cid & 31;
    int sl, ck;
    if (r < 8){ sl = 0; ck = r; }
    else if (r < 24){ sl = 1 + ((r-8)>>2); ck = (r-8)&3; }
    else { sl = 5 + ((r-24)>>1); ck = (r-24)&1; }
    int win = (sl==0)?0 : (sl<=2?1 : (sl<=4?2:3));
    int off = (sl==0)?0 : (sl==1?0 : (sl==2?1152 : (sl==3?0 : (sl==4?1152 : (sl-5)*576))));
    int grow = (batch*4 + win)*WL + off + ck*288;

    uint32_t smb = smem_u32(smw);
    const uint4* gk4 = (const uint4*)g_kwh;
    const uint4* gv4 = (const uint4*)g_vwh;

    float c[16][4];
    #pragma unroll
    for (int n=0;n<16;n++){ c[n][0]=0.f; c[n][1]=0.f; c[n][2]=0.f; c[n][3]=0.f; }
    float svacc = 0.f;

    uint32_t aOff = ((lane&7) + ((lane>>4)&1)*8)*272u + w*32u + ((lane>>3)&1)*16u;
    uint32_t bOff = ((lane&7) + ((lane>>3)&1)*8)*272u + ((lane>>4)&1)*16u;

    {
        int row = tid >> 4, q16 = tid & 15;
        CP16(smb + (KT0 + row*68 + q16*4)*4, (const void*)(gk4 + (grow + row)*16 + q16));
        CP16(smb + (VT0 + row*68 + q16*4)*4, (const void*)(gv4 + (grow + row)*16 + q16));
        CP_COMMIT;
    }
    CP_WAIT0;
    __syncthreads();

    const unsigned short* sp = (const unsigned short*)smw;

    for (int it=0; it<18; it++){
        int cK = (it&1) ? KT1 : KT0;
        int cV = (it&1) ? VT1 : VT0;
        int nK = (it&1) ? KT0 : KT1;
        int nV = (it&1) ? VT0 : VT1;
        if (it+1 < 18){
            int row = tid >> 4, q16 = tid & 15;
            int gr = grow + (it+1)*16 + row;
            CP16(smb + (nK + row*68 + q16*4)*4, (const void*)(gk4 + gr*16 + q16));
            CP16(smb + (nV + row*68 + q16*4)*4, (const void*)(gv4 + gr*16 + q16));
            CP_COMMIT;
        }
        unsigned a0,a1,a2,a3;
        LDM_X4T(a0,a1,a2,a3, smb + cV*4 + aOff);
        #pragma unroll
        for (int ng2=0; ng2<8; ng2++){
            unsigned b0,b1,b2,b3;
            LDM_X4T(b0,b1,b2,b3, smb + cK*4 + bOff + ng2*32);
            MMA_BF16(c[2*ng2],   a0,a1,a2,a3, b0,b1);
            MMA_BF16(c[2*ng2+1], a0,a1,a2,a3, b2,b3);
        }
        {
            int base = (tid < 128) ? (cK*2 + tid) : (cV*2 + (tid-128));
            #pragma unroll
            for (int rr=0; rr<16; rr++){
                unsigned short hv = sp[base + rr*136];
                svacc += __bfloat162float(*(__nv_bfloat16*)&hv);
            }
        }
        CP_WAIT0;
        __syncthreads();
    }

    unsigned* pb = g_Ppart + cid*8192;
    int d2a = w*16 + q, d2b = d2a + 8;
    #pragma unroll
    for (int ng=0; ng<16; ng++){
        int u = ng*4 + c4;
        PACK_BF2(pb[d2a*64 + u], c[ng][0], c[ng][1]);
        PACK_BF2(pb[d2b*64 + u], c[ng][2], c[ng][3]);
    }
    if (tid < 128) g_ksp[cid*128 + tid] = svacc;
    else           g_vsp[cid*128 + (tid-128)] = svacc;
}

// ============ K2c: reduce bf16 partials -> bf16 frag-ordered Mt (grid 36x8) ============
__global__ void k2c_reduce(){
    int s = blockIdx.x;
    int part = blockIdx.y;
    int batch = s / 9, sl = s - batch*9;
    int cb, nch;
    if (sl == 0){ cb = 0; nch = 8; }
    else if (sl < 5){ cb = 8 + (sl-1)*4; nch = 4; }
    else { cb = 24 + (sl-5)*2; nch = 2; }
    cb += batch*32;
    int tid = threadIdx.x;

    #pragma unroll
    for (int e=0; e<4; e++){
        int idx = part*1024 + tid + e*256;
        int n = idx >> 6, f = idx & 63;
        int kk = f >> 3, rr = f & 7;
        int c4v = rr >> 1, h = rr & 1;
        int u = kk*8 + h*4 + c4v;
        float s0 = 0.f, s1 = 0.f;
        #pragma unroll 4
        for (int cc=0; cc<nch; cc++){
            unsigned pv = g_Ppart[(cb+cc)*8192 + n*64 + u];
            __nv_bfloat162 hb = *(__nv_bfloat162*)&pv;
            s0 += __low2float(hb); s1 += __high2float(hb);
        }
        __nv_bfloat162 hh = __floats2bfloat162_rn(s0, s1);
        g_Mt[s*8192 + idx] = *(unsigned*)&hh;
    }
    if (part == 0){
        if (tid < 128){
            float a = 0.f;
            for (int cc=0; cc<nch; cc++) a += g_ksp[(cb+cc)*128 + tid];
            g_ksum[s*128 + tid] = a;
        } else {
            int t = tid - 128;
            float a = 0.f;
            for (int cc=0; cc<nch; cc++) a += g_vsp[(cb+cc)*128 + t];
            g_vsum[s*128 + t] = a;
        }
    }
}

// ============ K2b: O = (vsum + SCALE*Q@Mt)/l * gate, scatter natural bf16 ============
__global__ void __launch_bounds__(256)
k2b_qm(){
    int tid = threadIdx.x, lane = tid & 31, w = tid >> 5;
    int q = lane >> 2, c4 = lane & 3;
    int r0 = w*16 + q;
    int bx = blockIdx.x, batch = blockIdx.y;
    int sl, qt;
    if (bx < 18){ sl = 0; qt = bx; }
    else if (bx < 54){ int e = bx - 18; sl = 1 + e/9; qt = e - (sl-1)*9; }
    else { int e = bx - 54; sl = 5 + e/5; qt = e - (sl-5)*5; }
    int win = (sl==0)?0 : (sl<=2?1 : (sl<=4?2:3));
    int off = (sl==0)?0 : (sl==1?0 : (sl==2?1152 : (sl==3?0 : (sl==4?1152 : (sl-5)*576))));
    int len = (sl==0)?2304 : (sl<5?1152:576);
    int gsb = (batch*4 + win)*WL + off;

    int ra = qt*128 + r0;
    int rb = ra + 8;
    int va = ra < len, vb = rb < len;
    int rac = va ? ra : len-1;
    int rbc = vb ? rb : len-1;

    unsigned aq[8][4];
    {
        const unsigned* qp = (const unsigned*)g_qwh;
        int rA = (gsb + rac)*64, rB = (gsb + rbc)*64;
        #pragma unroll
        for (int kk=0;kk<8;kk++){
            aq[kk][0] = qp[rA + kk*8 + c4];
            aq[kk][1] = qp[rB + kk*8 + c4];
            aq[kk][2] = qp[rA + kk*8 + c4 + 4];
            aq[kk][3] = qp[rB + kk*8 + c4 + 4];
        }
    }

    const unsigned* MtS = g_Mt  + (batch*9 + sl)*8192;
    const float*    ksS = g_ksum + (batch*9 + sl)*128;
    const float*    vsS = g_vsum + (batch*9 + sl)*128;

    float c[16][4];
    #pragma unroll
    for (int n=0;n<16;n++){ c[n][0]=0.f; c[n][1]=0.f; c[n][2]=0.f; c[n][3]=0.f; }
    #pragma unroll
    for (int kk=0;kk<8;kk++){
        #pragma unroll
        for (int ng=0; ng<16; ng++){
            uint2 bb = *(const uint2*)(MtS + (ng*8+q)*64 + kk*8 + c4*2);
            MMA_BF16(c[ng], aq[kk][0],aq[kk][1],aq[kk][2],aq[kk][3], bb.x, bb.y);
        }
    }

    float d0 = 0.f, d1 = 0.f;
    #pragma unroll
    for (int kk=0;kk<8;kk++){
        #pragma unroll
        for (int h=0; h<2; h++){
            float2 ks2 = *(const float2*)(ksS + kk*16 + h*8 + 2*c4);
            unsigned ua = aq[kk][h*2], ub = aq[kk][h*2+1];
            __nv_bfloat162 ha = *(__nv_bfloat162*)&ua;
            __nv_bfloat162 hb = *(__nv_bfloat162*)&ub;
            d0 += __low2float(ha)*ks2.x + __high2float(ha)*ks2.y;
            d1 += __low2float(hb)*ks2.x + __high2float(hb)*ks2.y;
        }
    }
    d0 += __shfl_xor_sync(0xffffffffu, d0, 1);
    d0 += __shfl_xor_sync(0xffffffffu, d0, 2);
    d1 += __shfl_xor_sync(0xffffffffu, d1, 1);
    d1 += __shfl_xor_sync(0xffffffffu, d1, 2);
    float inv0 = __fdividef(1.f, (float)len + SCALE_S*d0);
    float inv1 = __fdividef(1.f, (float)len + SCALE_S*d1);

    int natr0 = va ? nat_from_reg(batch, win, off + ra) : 0;
    int natr1 = vb ? nat_from_reg(batch, win, off + rb) : 0;

    #pragma unroll
    for (int ng=0; ng<16; ng++){
        int col = ng*8 + 2*c4;
        float2 vs2 = *(const float2*)(vsS + col);
        if (va){
            float2 g2 = *(const float2*)(g_gate + natr0*128 + col);
            float ox = (vs2.x + SCALE_S*c[ng][0])*inv0*g2.x;
            float oy = (vs2.y + SCALE_S*c[ng][1])*inv0*g2.y;
            __nv_bfloat162 hh = __floats2bfloat162_rn(ox, oy);
            g_atth[natr0*64 + ng*4 + c4] = *(unsigned*)&hh;
        }
        if (vb){
            float2 g2 = *(const float2*)(g_gate + natr1*128 + col);
            float ox = (vs2.x + SCALE_S*c[ng][2])*inv1*g2.x;
            float oy = (vs2.y + SCALE_S*c[ng][3])*inv1*g2.y;
            __nv_bfloat162 hh = __floats2bfloat162_rn(ox, oy);
            g_atth[natr1*64 + ng*4 + c4] = *(unsigned*)&hh;
        }
    }
}

// ====== K3: bf16 silu(X@W1+b1)@W2 + residual, staged coalesced epilogue ======
__global__ void __launch_bounds__(256)
out_kernel(const float* __restrict__ b1, const float* __restrict__ src,
           float* __restrict__ outp, int copies){
    extern __shared__ unsigned smu[];
    unsigned* Ah = smu;
    unsigned* Xs = smu + OU_XS3;
    float* F = (float*)smu;            // reuse whole smem for fp32 staging [128][132]
    int tid = threadIdx.x, lane = tid & 31, w = tid >> 5;
    int q = lane >> 2, c4 = lane & 3;
    int wr = w >> 1, wc = w & 1;
    int mbase = blockIdx.x * 128;
    uint32_t smbA = smem_u32(Ah);
    uint32_t smbX = smem_u32(Xs);

    #pragma unroll
    for (int it=0; it<16; it++){
        int idx = tid + it*256; int row = idx>>5, cq = idx&31;
        uint2 v = ((const uint2*)g_atth)[(size_t)(mbase+row)*32 + cq];
        *(uint2*)&Ah[row*68 + cq*2] = v;
    }
    __syncthreads();

    int lrow = (lane&7) + ((lane>>3)&1)*8;
    int lcolb = ((lane>>4)&1)*16;

    const unsigned* WB1 = g_wprep + 32768;
    float c[2][8][4];
    #pragma unroll
    for (int n=0;n<8;n++){
        int col = wc*64 + n*8 + 2*c4;
        float bb0 = b1[col], bb1v = b1[col+1];
        c[0][n][0]=bb0; c[0][n][1]=bb1v; c[0][n][2]=bb0; c[0][n][3]=bb1v;
        c[1][n][0]=bb0; c[1][n][1]=bb1v; c[1][n][2]=bb0; c[1][n][3]=bb1v;
    }
    #pragma unroll
    for (int kk=0;kk<8;kk++){
        unsigned a[2][4];
        #pragma unroll
        for (int mm=0;mm<2;mm++){
            int row = wr*32 + mm*16 + lrow;
            LDM_X4(a[mm][0],a[mm][1],a[mm][2],a[mm][3], smbA + row*272 + kk*32 + lcolb);
        }
        #pragma unroll
        for (int n=0;n<8;n++){
            int nabs = wc*64 + n*8 + q;
            uint2 bb = *(const uint2*)(WB1 + nabs*64 + kk*8 + c4*2);
            MMA_BF16(c[0][n], a[0][0],a[0][1],a[0][2],a[0][3], bb.x, bb.y);
            MMA_BF16(c[1][n], a[1][0],a[1][1],a[1][2],a[1][3], bb.x, bb.y);
        }
    }
    #pragma unroll
    for (int mm=0;mm<2;mm++){
        int r1 = wr*32 + q + mm*16;
        #pragma unroll
        for (int n=0;n<8;n++){
            int ci = wc*32 + n*4 + c4;
            __nv_bfloat162 h0 = __floats2bfloat162_rn(siluf(c[mm][n][0]), siluf(c[mm][n][1]));
            __nv_bfloat162 h1 = __floats2bfloat162_rn(siluf(c[mm][n][2]), siluf(c[mm][n][3]));
            Xs[r1*68 + ci]     = *(unsigned*)&h0;
            Xs[(r1+8)*68 + ci] = *(unsigned*)&h1;
        }
    }
    __syncthreads();

    const unsigned* WB2 = g_wprep + 40960;
    float c2[2][8][4];
    #pragma unroll
    for (int mm=0;mm<2;mm++)
        #pragma unroll
        for (int n=0;n<8;n++){ c2[mm][n][0]=0.f; c2[mm][n][1]=0.f; c2[mm][n][2]=0.f; c2[mm][n][3]=0.f; }
    #pragma unroll
    for (int kk=0;kk<8;kk++){
        unsigned a[2][4];
        #pragma unroll
        for (int mm=0;mm<2;mm++){
            int row = wr*32 + mm*16 + lrow;
            LDM_X4(a[mm][0],a[mm][1],a[mm][2],a[mm][3], smbX + row*272 + kk*32 + lcolb);
        }
        #pragma unroll
        for (int n=0;n<8;n++){
            int nabs = wc*64 + n*8 + q;
            uint2 bb = *(const uint2*)(WB2 + nabs*64 + kk*8 + c4*2);
            MMA_BF16(c2[0][n], a[0][0],a[0][1],a[0][2],a[0][3], bb.x, bb.y);
            MMA_BF16(c2[1][n], a[1][0],a[1][1],a[1][2],a[1][3], bb.x, bb.y);
        }
    }
    // stage GEMM2 result (fragment layout) into fp32 smem, then coalesced out
    __syncthreads();   // all warps done reading Ah/Xs before overwrite
    #pragma unroll
    for (int mm=0;mm<2;mm++){
        int r1 = wr*32 + q + mm*16;
        #pragma unroll
        for (int n=0;n<8;n++){
            int col = wc*64 + n*8 + 2*c4;
            *(float2*)&F[r1*132 + col]     = make_float2(c2[mm][n][0], c2[mm][n][1]);
            *(float2*)&F[(r1+8)*132 + col] = make_float2(c2[mm][n][2], c2[mm][n][3]);
        }
    }
    __syncthreads();
    #pragma unroll
    for (int it=0; it<16; it++){
        int idx = tid + it*256; int row = idx>>5, cq = idx&31;
        float4 f = *(float4*)&F[row*132 + cq*4];
        float4 s = ((const float4*)src)[(size_t)(mbase+row)*32 + cq];
        f.x += s.x; f.y += s.y; f.z += s.z; f.w += s.w;
        for (int cp=0; cp<copies; cp++)
            ((float4*)outp)[(size_t)cp*ROWS_T*32 + (size_t)(mbase+row)*32 + cq] = f;
    }
}

extern "C" void kernel_launch(void* const* d_in, const int* in_sizes, int n_in,
                              void* d_out, int out_size){
    int o = (n_in >= 14 && in_sizes[3] == 1) ? 2 : 0;
    const float* source = (const float*)d_in[0];
    const float* ln_g   = (const float*)d_in[3+o];
    const float* ln_b   = (const float*)d_in[4+o];
    const float* w_gq   = (const float*)d_in[5+o];
    const float* b_gq   = (const float*)d_in[6+o];
    const float* w_kv   = (const float*)d_in[7+o];
    const float* b_kv   = (const float*)d_in[8+o];
    const float* w_o1   = (const float*)d_in[9+o];
    const float* b_o1   = (const float*)d_in[10+o];
    const float* w_o2   = (const float*)d_in[11+o];
    int copies = out_size / (ROWS_T*128);
    if (copies < 1) copies = 1;

    static int attr_done = 0;
    if (!attr_done){
        cudaFuncSetAttribute(proj_fused, cudaFuncAttributeMaxDynamicSharedMemorySize, PROJ_SMEM3);
        cudaFuncSetAttribute(k2a_mt,     cudaFuncAttributeMaxDynamicSharedMemorySize, K2A_SMEM);
        cudaFuncSetAttribute(out_kernel, cudaFuncAttributeMaxDynamicSharedMemorySize, OUT_SMEM3);
        attr_done = 1;
    }

    prep_w<<<192, 256>>>(w_gq, w_kv, w_o1, w_o2);
    proj_fused<<<ROWS_T/128, 256, PROJ_SMEM3>>>(source, ln_g, ln_b, b_gq, b_kv);
    k2a_mt<<<128, 256, K2A_SMEM>>>();
    k2c_reduce<<<dim3(36, 8), 256>>>();
    k2b_qm<<<dim3(74, 4), 256>>>();
    out_kernel<<<ROWS_T/128, 256, OUT_SMEM3>>>(b_o1, source, (float*)d_out, copies);
}

// round 14
// speedup vs baseline: 1.0919x; 1.0919x over previous
#include <cuda_runtime.h>
#include <cuda_bf16.h>
#include <cstdint>

#define ROWS_T 36864
#define SEQ    9216
#define WL     2304
#define SCALE_S (1.0f/1179648.0f)

// proj smem (64-row tile): Ah u32[64][68] then S32 float[64][132]
#define PJ_S32 4352
#define PROJ_SMEM3 ((4352 + 8448)*4)
// out smem (64-row tile): Ah u32[64][68], Xs u32[64][68]
#define OU_XS3 4352
#define OUT_SMEM3 ((4352 + 4352)*4)
#define KT0 0
#define VT0 1088
#define KT1 2176
#define VT1 3264
#define K2A_SMEM (4352*4)

__device__ float g_gate[ROWS_T*128];
__device__ unsigned short g_qwh[ROWS_T*128];
__device__ unsigned short g_kwh[ROWS_T*128];
__device__ unsigned short g_vwh[ROWS_T*128];
__device__ unsigned g_wprep[49152];
__device__ unsigned g_Ppart[128*8192];
__device__ float g_ksp[128*128];
__device__ float g_vsp[128*128];
__device__ unsigned g_Mt[36*8192];
__device__ float g_ksum[36*128];
__device__ float g_vsum[36*128];
__device__ unsigned g_atth[ROWS_T*64];

__device__ __forceinline__ float siluf(float x){ return x / (1.0f + __expf(-x)); }

__device__ __forceinline__ int win_from_nat(int r){
    int b = r / SEQ; int p = r - b*SEQ;
    int y = p / 96, x = p - y*96;
    int yr = y + 72; if (yr >= 96) yr -= 96;
    int xr = x + 72; if (xr >= 96) xr -= 96;
    int wy = yr / 48, iy = yr - wy*48;
    int wx = xr / 48, ix = xr - wx*48;
    int w = wy*2 + wx;
    int j;
    if (w == 0)      j = iy*48 + ix;
    else if (w == 1){ int sx = ix >= 24; j = sx*1152 + iy*24 + (ix - sx*24); }
    else if (w == 2){ int sy = iy >= 24; j = sy*1152 + (iy - sy*24)*48 + ix; }
    else { int sy = iy >= 24, sx = ix >= 24;
           j = (sy*2+sx)*576 + (iy - sy*24)*24 + (ix - sx*24); }
    return (b*4 + w)*WL + j;
}
__device__ __forceinline__ int nat_from_reg(int batch, int wv, int wrem){
    int wy = wv >> 1, wx = wv & 1;
    int iy, ix;
    if (wv == 0){ iy = wrem/48; ix = wrem - iy*48; }
    else if (wv == 1){ int sx = wrem >= 1152; int t = wrem - sx*1152; iy = t/24; ix = sx*24 + (t - iy*24); }
    else if (wv == 2){ int sy = wrem >= 1152; int t = wrem - sy*1152; int r = t/48; iy = sy*24 + r; ix = t - r*48; }
    else { int sg = wrem/576; int t = wrem - sg*576; int sy = sg>>1, sx = sg&1;
           int r = t/24; iy = sy*24 + r; ix = sx*24 + (t - r*24); }
    int y = wy*48 + iy + 24; if (y >= 96) y -= 96;
    int x = wx*48 + ix + 24; if (x >= 96) x -= 96;
    return batch*SEQ + y*96 + x;
}

__device__ __forceinline__ uint32_t smem_u32(const void* p){
    uint32_t a;
    asm("{ .reg .u64 t; cvta.to.shared.u64 t, %1; cvt.u32.u64 %0, t; }" : "=r"(a) : "l"(p));
    return a;
}

#define MMA_BF16(c, a0,a1,a2,a3, b0,b1) \
    asm volatile("mma.sync.aligned.m16n8k16.row.col.f32.bf16.bf16.f32 " \
        "{%0,%1,%2,%3},{%4,%5,%6,%7},{%8,%9},{%0,%1,%2,%3};" \
        : "+f"((c)[0]),"+f"((c)[1]),"+f"((c)[2]),"+f"((c)[3]) \
        : "r"(a0),"r"(a1),"r"(a2),"r"(a3),"r"(b0),"r"(b1))

#define LDM_X4(b0,b1,b2,b3,addr) \
    asm volatile("ldmatrix.sync.aligned.m8n8.x4.shared.b16 {%0,%1,%2,%3}, [%4];" \
        : "=r"(b0),"=r"(b1),"=r"(b2),"=r"(b3) : "r"(addr))
#define LDM_X4T(b0,b1,b2,b3,addr) \
    asm volatile("ldmatrix.sync.aligned.m8n8.x4.trans.shared.b16 {%0,%1,%2,%3}, [%4];" \
        : "=r"(b0),"=r"(b1),"=r"(b2),"=r"(b3) : "r"(addr))

#define CP16(dst, src) \
    asm volatile("cp.async.cg.shared.global [%0], [%1], 16;" :: "r"(dst), "l"(src))
#define CP_COMMIT asm volatile("cp.async.commit_group;")
#define CP_WAIT0  asm volatile("cp.async.wait_group 0;")

#define PACK_BF2(u, x, y) do { __nv_bfloat162 _h = __floats2bfloat162_rn((x),(y)); (u) = *(unsigned*)&_h; } while(0)

// ============ K0: weight prep ============
__global__ void prep_w(const float* __restrict__ gq, const float* __restrict__ kv,
                       const float* __restrict__ o1, const float* __restrict__ o2){
    int id = blockIdx.x*256 + threadIdx.x;
    const float* W; int rem, ncols;
    if (id < 32768){ W = (id < 16384) ? gq : kv; ncols = 256; rem = id & 16383; }
    else           { W = (id < 40960) ? o1 : o2; ncols = 128; rem = id & 8191; }
    int n  = rem >> 6;
    int r  = rem & 63;
    int kk = r >> 3, c4 = (r >> 1) & 3, h = r & 1;
    int k0 = kk*16 + h*8 + 2*c4;
    __nv_bfloat162 hh = __floats2bfloat162_rn(W[k0*ncols + n], W[(k0+1)*ncols + n]);
    g_wprep[id] = *(unsigned*)&hh;
}

// ==== K1: fused LN + (gate,Q,K,V) bf16 projection, 64-row tiles (grid 576) ====
__global__ void __launch_bounds__(256)
proj_fused(const float* __restrict__ src, const float* __restrict__ lg, const float* __restrict__ lb,
           const float* __restrict__ b_gq, const float* __restrict__ b_kv){
    extern __shared__ unsigned smu[];
    float* S32 = (float*)(smu + PJ_S32);   // [64][132]
    int tid = threadIdx.x, lane = tid & 31, w = tid >> 5;
    int q = lane >> 2, c4 = lane & 3;
    int wr = w >> 2, wc = w & 3;           // wr: 2 row-groups of 32; wc: 4 col-quarters of 32
    int mbase = blockIdx.x * 64;
    uint32_t smb = smem_u32(smu);

    const float4* Sg = ((const float4*)src) + mbase*32;
    #pragma unroll
    for (int it=0; it<8; it++){
        int idx = tid + it*256; int row = idx>>5, cq = idx&31;
        *(float4*)&S32[row*132 + cq*4] = Sg[idx];
    }
    __syncthreads();
    if (tid < 64){
        float s=0.f, s2=0.f;
        #pragma unroll
        for (int i=0;i<32;i++){
            float4 v = *(float4*)&S32[tid*132 + i*4];
            s += v.x+v.y+v.z+v.w;
            s2 += v.x*v.x+v.y*v.y+v.z*v.z+v.w*v.w;
        }
        float mean = s*(1.f/128.f);
        float var  = s2*(1.f/128.f) - mean*mean;
        float rs   = rsqrtf(var + 1e-5f);
        #pragma unroll
        for (int i=0;i<32;i++){
            float4 v = *(float4*)&S32[tid*132 + i*4];
            float4 g4 = ((const float4*)lg)[i];
            float4 b4 = ((const float4*)lb)[i];
            float x0 = (v.x-mean)*rs*g4.x + b4.x;
            float x1 = (v.y-mean)*rs*g4.y + b4.y;
            float x2 = (v.z-mean)*rs*g4.z + b4.z;
            float x3 = (v.w-mean)*rs*g4.w + b4.w;
            __nv_bfloat162 h0 = __floats2bfloat162_rn(x0, x1);
            __nv_bfloat162 h1 = __floats2bfloat162_rn(x2, x3);
            uint2 u; u.x = *(unsigned*)&h0; u.y = *(unsigned*)&h1;
            *(uint2*)&smu[tid*68 + i*2] = u;
        }
    }
    __syncthreads();

    int lrow = (lane&7) + ((lane>>3)&1)*8;
    int lcolb = ((lane>>4)&1)*16;

    for (int nt=0; nt<4; nt++){
        const unsigned* WB = g_wprep + nt*8192;
        const float* bias  = (nt<2) ? (b_gq + nt*128) : (b_kv + (nt-2)*128);

        float c[2][4][4];
        #pragma unroll
        for (int n=0;n<4;n++){
            int col = wc*32 + n*8 + 2*c4;
            float bb0 = bias[col], bb1 = bias[col+1];
            c[0][n][0]=bb0; c[0][n][1]=bb1; c[0][n][2]=bb0; c[0][n][3]=bb1;
            c[1][n][0]=bb0; c[1][n][1]=bb1; c[1][n][2]=bb0; c[1][n][3]=bb1;
        }
        #pragma unroll
        for (int kk=0;kk<8;kk++){
            unsigned a[2][4];
            #pragma unroll
            for (int mm=0;mm<2;mm++){
                int row = wr*32 + mm*16 + lrow;
                LDM_X4(a[mm][0],a[mm][1],a[mm][2],a[mm][3], smb + row*272 + kk*32 + lcolb);
            }
            #pragma unroll
            for (int n=0;n<4;n++){
                int nabs = wc*32 + n*8 + q;
                uint2 bb = *(const uint2*)(WB + nabs*64 + kk*8 + c4*2);
                MMA_BF16(c[0][n], a[0][0],a[0][1],a[0][2],a[0][3], bb.x, bb.y);
                MMA_BF16(c[1][n], a[1][0],a[1][1],a[1][2],a[1][3], bb.x, bb.y);
            }
        }

        if (nt == 0){
            #pragma unroll
            for (int mm=0;mm<2;mm++){
                int r1 = mbase + wr*32 + q + mm*16;
                #pragma unroll
                for (int n=0;n<4;n++){
                    int col = wc*32 + n*8 + 2*c4;
                    float2 y0 = { siluf(c[mm][n][0]), siluf(c[mm][n][1]) };
                    float2 y1 = { siluf(c[mm][n][2]), siluf(c[mm][n][3]) };
                    *(float2*)(g_gate + r1*128 + col)     = y0;
                    *(float2*)(g_gate + (r1+8)*128 + col) = y1;
                }
            }
        } else {
            unsigned short* oh = (nt==1) ? g_qwh : (nt==2 ? g_kwh : g_vwh);
            #pragma unroll
            for (int mm=0;mm<2;mm++){
                int r1 = mbase + wr*32 + q + mm*16;
                int dr1 = win_from_nat(r1);
                int dr2 = win_from_nat(r1+8);
                #pragma unroll
                for (int n=0;n<4;n++){
                    int col = wc*32 + n*8 + 2*c4;
                    __nv_bfloat162 h0 = __floats2bfloat162_rn(siluf(c[mm][n][0]), siluf(c[mm][n][1]));
                    __nv_bfloat162 h1 = __floats2bfloat162_rn(siluf(c[mm][n][2]), siluf(c[mm][n][3]));
                    *(__nv_bfloat162*)(oh + dr1*128 + col) = h0;
                    *(__nv_bfloat162*)(oh + dr2*128 + col) = h1;
                }
            }
        }
    }
}

// ============ K2a: per-chunk partial P[d2][d1] (bf16 partial store) ============
__global__ void __launch_bounds__(256)
k2a_mt(){
    extern __shared__ unsigned smw[];
    int tid = threadIdx.x, lane = tid & 31, w = tid >> 5;
    int q = lane >> 2, c4 = lane & 3;
    int cid = blockIdx.x;
    int batch = cid >> 5, r = cid & 31;
    int sl, ck;
    if (r < 8){ sl = 0; ck = r; }
    else if (r < 24){ sl = 1 + ((r-8)>>2); ck = (r-8)&3; }
    else { sl = 5 + ((r-24)>>1); ck = (r-24)&1; }
    int win = (sl==0)?0 : (sl<=2?1 : (sl<=4?2:3));
    int off = (sl==0)?0 : (sl==1?0 : (sl==2?1152 : (sl==3?0 : (sl==4?1152 : (sl-5)*576))));
    int grow = (batch*4 + win)*WL + off + ck*288;

    uint32_t smb = smem_u32(smw);
    const uint4* gk4 = (const uint4*)g_kwh;
    const uint4* gv4 = (const uint4*)g_vwh;

    float c[16][4];
    #pragma unroll
    for (int n=0;n<16;n++){ c[n][0]=0.f; c[n][1]=0.f; c[n][2]=0.f; c[n][3]=0.f; }
    float svacc = 0.f;

    uint32_t aOff = ((lane&7) + ((lane>>4)&1)*8)*272u + w*32u + ((lane>>3)&1)*16u;
    uint32_t bOff = ((lane&7) + ((lane>>3)&1)*8)*272u + ((lane>>4)&1)*16u;

    {
        int row = tid >> 4, q16 = tid & 15;
        CP16(smb + (KT0 + row*68 + q16*4)*4, (const void*)(gk4 + (grow + row)*16 + q16));
        CP16(smb + (VT0 + row*68 + q16*4)*4, (const void*)(gv4 + (grow + row)*16 + q16));
        CP_COMMIT;
    }
    CP_WAIT0;
    __syncthreads();

    const unsigned short* sp = (const unsigned short*)smw;

    for (int it=0; it<18; it++){
        int cK = (it&1) ? KT1 : KT0;
        int cV = (it&1) ? VT1 : VT0;
        int nK = (it&1) ? KT0 : KT1;
        int nV = (it&1) ? VT0 : VT1;
        if (it+1 < 18){
            int row = tid >> 4, q16 = tid & 15;
            int gr = grow + (it+1)*16 + row;
            CP16(smb + (nK + row*68 + q16*4)*4, (const void*)(gk4 + gr*16 + q16));
            CP16(smb + (nV + row*68 + q16*4)*4, (const void*)(gv4 + gr*16 + q16));
            CP_COMMIT;
        }
        unsigned a0,a1,a2,a3;
        LDM_X4T(a0,a1,a2,a3, smb + cV*4 + aOff);
        #pragma unroll
        for (int ng2=0; ng2<8; ng2++){
            unsigned b0,b1,b2,b3;
            LDM_X4T(b0,b1,b2,b3, smb + cK*4 + bOff + ng2*32);
            MMA_BF16(c[2*ng2],   a0,a1,a2,a3, b0,b1);
            MMA_BF16(c[2*ng2+1], a0,a1,a2,a3, b2,b3);
        }
        {
            int base = (tid < 128) ? (cK*2 + tid) : (cV*2 + (tid-128));
            #pragma unroll
            for (int rr=0; rr<16; rr++){
                unsigned short hv = sp[base + rr*136];
                svacc += __bfloat162float(*(__nv_bfloat16*)&hv);
            }
        }
        CP_WAIT0;
        __syncthreads();
    }

    unsigned* pb = g_Ppart + cid*8192;
    int d2a = w*16 + q, d2b = d2a + 8;
    #pragma unroll
    for (int ng=0; ng<16; ng++){
        int u = ng*4 + c4;
        PACK_BF2(pb[d2a*64 + u], c[ng][0], c[ng][1]);
        PACK_BF2(pb[d2b*64 + u], c[ng][2], c[ng][3]);
    }
    if (tid < 128) g_ksp[cid*128 + tid] = svacc;
    else           g_vsp[cid*128 + (tid-128)] = svacc;
}

// ============ K2c: reduce bf16 partials -> bf16 frag-ordered Mt (grid 36x8) ============
__global__ void k2c_reduce(){
    int s = blockIdx.x;
    int part = blockIdx.y;
    int batch = s / 9, sl = s - batch*9;
    int cb, nch;
    if (sl == 0){ cb = 0; nch = 8; }
    else if (sl < 5){ cb = 8 + (sl-1)*4; nch = 4; }
    else { cb = 24 + (sl-5)*2; nch = 2; }
    cb += batch*32;
    int tid = threadIdx.x;

    #pragma unroll
    for (int e=0; e<4; e++){
        int idx = part*1024 + tid + e*256;
        int n = idx >> 6, f = idx & 63;
        int kk = f >> 3, rr = f & 7;
        int c4v = rr >> 1, h = rr & 1;
        int u = kk*8 + h*4 + c4v;
        float s0 = 0.f, s1 = 0.f;
        #pragma unroll 4
        for (int cc=0; cc<nch; cc++){
            unsigned pv = g_Ppart[(cb+cc)*8192 + n*64 + u];
            __nv_bfloat162 hb = *(__nv_bfloat162*)&pv;
            s0 += __low2float(hb); s1 += __high2float(hb);
        }
        __nv_bfloat162 hh = __floats2bfloat162_rn(s0, s1);
        g_Mt[s*8192 + idx] = *(unsigned*)&hh;
    }
    if (part == 0){
        if (tid < 128){
            float a = 0.f;
            for (int cc=0; cc<nch; cc++) a += g_ksp[(cb+cc)*128 + tid];
            g_ksum[s*128 + tid] = a;
        } else {
            int t = tid - 128;
            float a = 0.f;
            for (int cc=0; cc<nch; cc++) a += g_vsp[(cb+cc)*128 + t];
            g_vsum[s*128 + t] = a;
        }
    }
}

// ============ K2b: O = (vsum + SCALE*Q@Mt)/l * gate, scatter natural bf16 ============
__global__ void __launch_bounds__(256)
k2b_qm(){
    int tid = threadIdx.x, lane = tid & 31, w = tid >> 5;
    int q = lane >> 2, c4 = lane & 3;
    int r0 = w*16 + q;
    int bx = blockIdx.x, batch = blockIdx.y;
    int sl, qt;
    if (bx < 18){ sl = 0; qt = bx; }
    else if (bx < 54){ int e = bx - 18; sl = 1 + e/9; qt = e - (sl-1)*9; }
    else { int e = bx - 54; sl = 5 + e/5; qt = e - (sl-5)*5; }
    int win = (sl==0)?0 : (sl<=2?1 : (sl<=4?2:3));
    int off = (sl==0)?0 : (sl==1?0 : (sl==2?1152 : (sl==3?0 : (sl==4?1152 : (sl-5)*576))));
    int len = (sl==0)?2304 : (sl<5?1152:576);
    int gsb = (batch*4 + win)*WL + off;

    int ra = qt*128 + r0;
    int rb = ra + 8;
    int va = ra < len, vb = rb < len;
    int rac = va ? ra : len-1;
    int rbc = vb ? rb : len-1;

    unsigned aq[8][4];
    {
        const unsigned* qp = (const unsigned*)g_qwh;
        int rA = (gsb + rac)*64, rB = (gsb + rbc)*64;
        #pragma unroll
        for (int kk=0;kk<8;kk++){
            aq[kk][0] = qp[rA + kk*8 + c4];
            aq[kk][1] = qp[rB + kk*8 + c4];
            aq[kk][2] = qp[rA + kk*8 + c4 + 4];
            aq[kk][3] = qp[rB + kk*8 + c4 + 4];
        }
    }

    const unsigned* MtS = g_Mt  + (batch*9 + sl)*8192;
    const float*    ksS = g_ksum + (batch*9 + sl)*128;
    const float*    vsS = g_vsum + (batch*9 + sl)*128;

    float c[16][4];
    #pragma unroll
    for (int n=0;n<16;n++){ c[n][0]=0.f; c[n][1]=0.f; c[n][2]=0.f; c[n][3]=0.f; }
    #pragma unroll
    for (int kk=0;kk<8;kk++){
        #pragma unroll
        for (int ng=0; ng<16; ng++){
            uint2 bb = *(const uint2*)(MtS + (ng*8+q)*64 + kk*8 + c4*2);
            MMA_BF16(c[ng], aq[kk][0],aq[kk][1],aq[kk][2],aq[kk][3], bb.x, bb.y);
        }
    }

    float d0 = 0.f, d1 = 0.f;
    #pragma unroll
    for (int kk=0;kk<8;kk++){
        #pragma unroll
        for (int h=0; h<2; h++){
            float2 ks2 = *(const float2*)(ksS + kk*16 + h*8 + 2*c4);
            unsigned ua = aq[kk][h*2], ub = aq[kk][h*2+1];
            __nv_bfloat162 ha = *(__nv_bfloat162*)&ua;
            __nv_bfloat162 hb = *(__nv_bfloat162*)&ub;
            d0 += __low2float(ha)*ks2.x + __high2float(ha)*ks2.y;
            d1 += __low2float(hb)*ks2.x + __high2float(hb)*ks2.y;
        }
    }
    d0 += __shfl_xor_sync(0xffffffffu, d0, 1);
    d0 += __shfl_xor_sync(0xffffffffu, d0, 2);
    d1 += __shfl_xor_sync(0xffffffffu, d1, 1);
    d1 += __shfl_xor_sync(0xffffffffu, d1, 2);
    float inv0 = __fdividef(1.f, (float)len + SCALE_S*d0);
    float inv1 = __fdividef(1.f, (float)len + SCALE_S*d1);

    int natr0 = va ? nat_from_reg(batch, win, off + ra) : 0;
    int natr1 = vb ? nat_from_reg(batch, win, off + rb) : 0;

    #pragma unroll
    for (int ng=0; ng<16; ng++){
        int col = ng*8 + 2*c4;
        float2 vs2 = *(const float2*)(vsS + col);
        if (va){
            float2 g2 = *(const float2*)(g_gate + natr0*128 + col);
            float ox = (vs2.x + SCALE_S*c[ng][0])*inv0*g2.x;
            float oy = (vs2.y + SCALE_S*c[ng][1])*inv0*g2.y;
            __nv_bfloat162 hh = __floats2bfloat162_rn(ox, oy);
            g_atth[natr0*64 + ng*4 + c4] = *(unsigned*)&hh;
        }
        if (vb){
            float2 g2 = *(const float2*)(g_gate + natr1*128 + col);
            float ox = (vs2.x + SCALE_S*c[ng][2])*inv1*g2.x;
            float oy = (vs2.y + SCALE_S*c[ng][3])*inv1*g2.y;
            __nv_bfloat162 hh = __floats2bfloat162_rn(ox, oy);
            g_atth[natr1*64 + ng*4 + c4] = *(unsigned*)&hh;
        }
    }
}

// ====== K3: bf16 silu(X@W1+b1)@W2 + residual, 64-row tiles (grid 576) ======
__global__ void __launch_bounds__(256)
out_kernel(const float* __restrict__ b1, const float* __restrict__ src,
           float* __restrict__ outp, int copies){
    extern __shared__ unsigned smu[];
    unsigned* Ah = smu;              // [64][68]
    unsigned* Xs = smu + OU_XS3;     // [64][68]
    int tid = threadIdx.x, lane = tid & 31, w = tid >> 5;
    int q = lane >> 2, c4 = lane & 3;
    int wr = w >> 2, wc = w & 3;
    int mbase = blockIdx.x * 64;
    uint32_t smbA = smem_u32(Ah);
    uint32_t smbX = smem_u32(Xs);

    #pragma unroll
    for (int it=0; it<8; it++){
        int idx = tid + it*256; int row = idx>>5, cq = idx&31;
        uint2 v = ((const uint2*)g_atth)[(size_t)(mbase+row)*32 + cq];
        *(uint2*)&Ah[row*68 + cq*2] = v;
    }
    __syncthreads();

    int lrow = (lane&7) + ((lane>>3)&1)*8;
    int lcolb = ((lane>>4)&1)*16;

    const unsigned* WB1 = g_wprep + 32768;
    float c[2][4][4];
    #pragma unroll
    for (int n=0;n<4;n++){
        int col = wc*32 + n*8 + 2*c4;
        float bb0 = b1[col], bb1v = b1[col+1];
        c[0][n][0]=bb0; c[0][n][1]=bb1v; c[0][n][2]=bb0; c[0][n][3]=bb1v;
        c[1][n][0]=bb0; c[1][n][1]=bb1v; c[1][n][2]=bb0; c[1][n][3]=bb1v;
    }
    #pragma unroll
    for (int kk=0;kk<8;kk++){
        unsigned a[2][4];
        #pragma unroll
        for (int mm=0;mm<2;mm++){
            int row = wr*32 + mm*16 + lrow;
            LDM_X4(a[mm][0],a[mm][1],a[mm][2],a[mm][3], smbA + row*272 + kk*32 + lcolb);
        }
        #pragma unroll
        for (int n=0;n<4;n++){
            int nabs = wc*32 + n*8 + q;
            uint2 bb = *(const uint2*)(WB1 + nabs*64 + kk*8 + c4*2);
            MMA_BF16(c[0][n], a[0][0],a[0][1],a[0][2],a[0][3], bb.x, bb.y);
            MMA_BF16(c[1][n], a[1][0],a[1][1],a[1][2],a[1][3], bb.x, bb.y);
        }
    }
    #pragma unroll
    for (int mm=0;mm<2;mm++){
        int r1 = wr*32 + q + mm*16;
        #pragma unroll
        for (int n=0;n<4;n++){
            int ci = wc*16 + n*4 + c4;
            __nv_bfloat162 h0 = __floats2bfloat162_rn(siluf(c[mm][n][0]), siluf(c[mm][n][1]));
            __nv_bfloat162 h1 = __floats2bfloat162_rn(siluf(c[mm][n][2]), siluf(c[mm][n][3]));
            Xs[r1*68 + ci]     = *(unsigned*)&h0;
            Xs[(r1+8)*68 + ci] = *(unsigned*)&h1;
        }
    }
    __syncthreads();

    const unsigned* WB2 = g_wprep + 40960;
    float c2[2][4][4];
    #pragma unroll
    for (int mm=0;mm<2;mm++)
        #pragma unroll
        for (int n=0;n<4;n++){ c2[mm][n][0]=0.f; c2[mm][n][1]=0.f; c2[mm][n][2]=0.f; c2[mm][n][3]=0.f; }
    #pragma unroll
    for (int kk=0;kk<8;kk++){
        unsigned a[2][4];
        #pragma unroll
        for (int mm=0;mm<2;mm++){
            int row = wr*32 + mm*16 + lrow;
            LDM_X4(a[mm][0],a[mm][1],a[mm][2],a[mm][3], smbX + row*272 + kk*32 + lcolb);
        }
        #pragma unroll
        for (int n=0;n<4;n++){
            int nabs = wc*32 + n*8 + q;
            uint2 bb = *(const uint2*)(WB2 + nabs*64 + kk*8 + c4*2);
            MMA_BF16(c2[0][n], a[0][0],a[0][1],a[0][2],a[0][3], bb.x, bb.y);
            MMA_BF16(c2[1][n], a[1][0],a[1][1],a[1][2],a[1][3], bb.x, bb.y);
        }
    }
    #pragma unroll
    for (int mm=0;mm<2;mm++){
        int r1 = mbase + wr*32 + q + mm*16;
        #pragma unroll
        for (int n=0;n<4;n++){
            int col = wc*32 + n*8 + 2*c4;
            float2 s0 = *(const float2*)(src + r1*128 + col);
            float2 s1 = *(const float2*)(src + (r1+8)*128 + col);
            float2 y0 = { c2[mm][n][0] + s0.x, c2[mm][n][1] + s0.y };
            float2 y1 = { c2[mm][n][2] + s1.x, c2[mm][n][3] + s1.y };
            for (int cp=0; cp<copies; cp++){
                *(float2*)(outp + (size_t)cp*ROWS_T*128 + r1*128 + col)     = y0;
                *(float2*)(outp + (size_t)cp*ROWS_T*128 + (r1+8)*128 + col) = y1;
            }
        }
    }
}

extern "C" void kernel_launch(void* const* d_in, const int* in_sizes, int n_in,
                              void* d_out, int out_size){
    int o = (n_in >= 14 && in_sizes[3] == 1) ? 2 : 0;
    const float* source = (const float*)d_in[0];
    const float* ln_g   = (const float*)d_in[3+o];
    const float* ln_b   = (const float*)d_in[4+o];
    const float* w_gq   = (const float*)d_in[5+o];
    const float* b_gq   = (const float*)d_in[6+o];
    const float* w_kv   = (const float*)d_in[7+o];
    const float* b_kv   = (const float*)d_in[8+o];
    const float* w_o1   = (const float*)d_in[9+o];
    const float* b_o1   = (const float*)d_in[10+o];
    const float* w_o2   = (const float*)d_in[11+o];
    int copies = out_size / (ROWS_T*128);
    if (copies < 1) copies = 1;

    static int attr_done = 0;
    if (!attr_done){
        cudaFuncSetAttribute(proj_fused, cudaFuncAttributeMaxDynamicSharedMemorySize, PROJ_SMEM3);
        cudaFuncSetAttribute(k2a_mt,     cudaFuncAttributeMaxDynamicSharedMemorySize, K2A_SMEM);
        cudaFuncSetAttribute(out_kernel, cudaFuncAttributeMaxDynamicSharedMemorySize, OUT_SMEM3);
        attr_done = 1;
    }

    prep_w<<<192, 256>>>(w_gq, w_kv, w_o1, w_o2);
    proj_fused<<<ROWS_T/64, 256, PROJ_SMEM3>>>(source, ln_g, ln_b, b_gq, b_kv);
    k2a_mt<<<128, 256, K2A_SMEM>>>();
    k2c_reduce<<<dim3(36, 8), 256>>>();
    k2b_qm<<<dim3(74, 4), 256>>>();
    out_kernel<<<ROWS_T/64, 256, OUT_SMEM3>>>(b_o1, source, (float*)d_out, copies);
}

// round 15
// speedup vs baseline: 1.1481x; 1.0515x over previous
#include <cuda_runtime.h>
#include <cuda_bf16.h>
#include <cstdint>

#define ROWS_T 36864
#define SEQ    9216
#define WL     2304
#define SCALE_S (1.0f/1179648.0f)

#define PJ_S32 8704
#define PROJ_SMEM3 ((8704 + 16896)*4)
#define OU_XS3 8704
#define OUT_SMEM3 ((8704 + 8704)*4)
#define KT0 0
#define VT0 1088
#define KT1 2176
#define VT1 3264
#define K2A_SMEM (4352*4)

__device__ float g_gate[ROWS_T*128];
__device__ unsigned short g_qwh[ROWS_T*128];
__device__ unsigned short g_kwh[ROWS_T*128];
__device__ unsigned short g_vwh[ROWS_T*128];
__device__ unsigned g_wprep[49152];
__device__ unsigned g_Ppart[256*8192];
__device__ float g_ksp[256*128];
__device__ float g_vsp[256*128];
__device__ unsigned g_Mt[36*8192];
__device__ float g_ksum[36*128];
__device__ float g_vsum[36*128];
__device__ unsigned g_atth[ROWS_T*64];

__device__ __forceinline__ float siluf(float x){ return x / (1.0f + __expf(-x)); }

__device__ __forceinline__ int win_from_nat(int r){
    int b = r / SEQ; int p = r - b*SEQ;
    int y = p / 96, x = p - y*96;
    int yr = y + 72; if (yr >= 96) yr -= 96;
    int xr = x + 72; if (xr >= 96) xr -= 96;
    int wy = yr / 48, iy = yr - wy*48;
    int wx = xr / 48, ix = xr - wx*48;
    int w = wy*2 + wx;
    int j;
    if (w == 0)      j = iy*48 + ix;
    else if (w == 1){ int sx = ix >= 24; j = sx*1152 + iy*24 + (ix - sx*24); }
    else if (w == 2){ int sy = iy >= 24; j = sy*1152 + (iy - sy*24)*48 + ix; }
    else { int sy = iy >= 24, sx = ix >= 24;
           j = (sy*2+sx)*576 + (iy - sy*24)*24 + (ix - sx*24); }
    return (b*4 + w)*WL + j;
}
__device__ __forceinline__ int nat_from_reg(int batch, int wv, int wrem){
    int wy = wv >> 1, wx = wv & 1;
    int iy, ix;
    if (wv == 0){ iy = wrem/48; ix = wrem - iy*48; }
    else if (wv == 1){ int sx = wrem >= 1152; int t = wrem - sx*1152; iy = t/24; ix = sx*24 + (t - iy*24); }
    else if (wv == 2){ int sy = wrem >= 1152; int t = wrem - sy*1152; int r = t/48; iy = sy*24 + r; ix = t - r*48; }
    else { int sg = wrem/576; int t = wrem - sg*576; int sy = sg>>1, sx = sg&1;
           int r = t/24; iy = sy*24 + r; ix = sx*24 + (t - r*24); }
    int y = wy*48 + iy + 24; if (y >= 96) y -= 96;
    int x = wx*48 + ix + 24; if (x >= 96) x -= 96;
    return batch*SEQ + y*96 + x;
}

__device__ __forceinline__ uint32_t smem_u32(const void* p){
    uint32_t a;
    asm("{ .reg .u64 t; cvta.to.shared.u64 t, %1; cvt.u32.u64 %0, t; }" : "=r"(a) : "l"(p));
    return a;
}

#define MMA_BF16(c, a0,a1,a2,a3, b0,b1) \
    asm volatile("mma.sync.aligned.m16n8k16.row.col.f32.bf16.bf16.f32 " \
        "{%0,%1,%2,%3},{%4,%5,%6,%7},{%8,%9},{%0,%1,%2,%3};" \
        : "+f"((c)[0]),"+f"((c)[1]),"+f"((c)[2]),"+f"((c)[3]) \
        : "r"(a0),"r"(a1),"r"(a2),"r"(a3),"r"(b0),"r"(b1))

#define LDM_X4(b0,b1,b2,b3,addr) \
    asm volatile("ldmatrix.sync.aligned.m8n8.x4.shared.b16 {%0,%1,%2,%3}, [%4];" \
        : "=r"(b0),"=r"(b1),"=r"(b2),"=r"(b3) : "r"(addr))
#define LDM_X4T(b0,b1,b2,b3,addr) \
    asm volatile("ldmatrix.sync.aligned.m8n8.x4.trans.shared.b16 {%0,%1,%2,%3}, [%4];" \
        : "=r"(b0),"=r"(b1),"=r"(b2),"=r"(b3) : "r"(addr))

#define CP16(dst, src) \
    asm volatile("cp.async.cg.shared.global [%0], [%1], 16;" :: "r"(dst), "l"(src))
#define CP_COMMIT asm volatile("cp.async.commit_group;")
#define CP_WAIT0  asm volatile("cp.async.wait_group 0;")

#define PACK_BF2(u, x, y) do { __nv_bfloat162 _h = __floats2bfloat162_rn((x),(y)); (u) = *(unsigned*)&_h; } while(0)

// ============ K0: weight prep ============
__global__ void prep_w(const float* __restrict__ gq, const float* __restrict__ kv,
                       const float* __restrict__ o1, const float* __restrict__ o2){
    int id = blockIdx.x*256 + threadIdx.x;
    const float* W; int rem, ncols;
    if (id < 32768){ W = (id < 16384) ? gq : kv; ncols = 256; rem = id & 16383; }
    else           { W = (id < 40960) ? o1 : o2; ncols = 128; rem = id & 8191; }
    int n  = rem >> 6;
    int r  = rem & 63;
    int kk = r >> 3, c4 = (r >> 1) & 3, h = r & 1;
    int k0 = kk*16 + h*8 + 2*c4;
    __nv_bfloat162 hh = __floats2bfloat162_rn(W[k0*ncols + n], W[(k0+1)*ncols + n]);
    g_wprep[id] = *(unsigned*)&hh;
}

// ============ K1: fused LN + (gate,Q,K,V) bf16 projection (R12/R9 version) ============
__global__ void __launch_bounds__(256)
proj_fused(const float* __restrict__ src, const float* __restrict__ lg, const float* __restrict__ lb,
           const float* __restrict__ b_gq, const float* __restrict__ b_kv){
    extern __shared__ unsigned smu[];
    float* S32 = (float*)(smu + PJ_S32);
    int tid = threadIdx.x, lane = tid & 31, w = tid >> 5;
    int q = lane >> 2, c4 = lane & 3;
    int wr = w >> 1, wc = w & 1;
    int mbase = blockIdx.x * 128;
    uint32_t smb = smem_u32(smu);

    const float4* Sg = ((const float4*)src) + mbase*32;
    #pragma unroll
    for (int it=0; it<16; it++){
        int idx = tid + it*256; int row = idx>>5, cq = idx&31;
        *(float4*)&S32[row*132 + cq*4] = Sg[idx];
    }
    __syncthreads();
    if (tid < 128){
        float s=0.f, s2=0.f;
        #pragma unroll
        for (int i=0;i<32;i++){
            float4 v = *(float4*)&S32[tid*132 + i*4];
            s += v.x+v.y+v.z+v.w;
            s2 += v.x*v.x+v.y*v.y+v.z*v.z+v.w*v.w;
        }
        float mean = s*(1.f/128.f);
        float var  = s2*(1.f/128.f) - mean*mean;
        float rs   = rsqrtf(var + 1e-5f);
        #pragma unroll
        for (int i=0;i<32;i++){
            float4 v = *(float4*)&S32[tid*132 + i*4];
            float4 g4 = ((const float4*)lg)[i];
            float4 b4 = ((const float4*)lb)[i];
            float x0 = (v.x-mean)*rs*g4.x + b4.x;
            float x1 = (v.y-mean)*rs*g4.y + b4.y;
            float x2 = (v.z-mean)*rs*g4.z + b4.z;
            float x3 = (v.w-mean)*rs*g4.w + b4.w;
            __nv_bfloat162 h0 = __floats2bfloat162_rn(x0, x1);
            __nv_bfloat162 h1 = __floats2bfloat162_rn(x2, x3);
            uint2 u; u.x = *(unsigned*)&h0; u.y = *(unsigned*)&h1;
            *(uint2*)&smu[tid*68 + i*2] = u;
        }
    }
    __syncthreads();

    int lrow = (lane&7) + ((lane>>3)&1)*8;
    int lcolb = ((lane>>4)&1)*16;

    for (int nt=0; nt<4; nt++){
        const unsigned* WB = g_wprep + nt*8192;
        const float* bias  = (nt<2) ? (b_gq + nt*128) : (b_kv + (nt-2)*128);

        float c[2][8][4];
        #pragma unroll
        for (int n=0;n<8;n++){
            int col = wc*64 + n*8 + 2*c4;
            float bb0 = bias[col], bb1 = bias[col+1];
            c[0][n][0]=bb0; c[0][n][1]=bb1; c[0][n][2]=bb0; c[0][n][3]=bb1;
            c[1][n][0]=bb0; c[1][n][1]=bb1; c[1][n][2]=bb0; c[1][n][3]=bb1;
        }
        #pragma unroll
        for (int kk=0;kk<8;kk++){
            unsigned a[2][4];
            #pragma unroll
            for (int mm=0;mm<2;mm++){
                int row = wr*32 + mm*16 + lrow;
                LDM_X4(a[mm][0],a[mm][1],a[mm][2],a[mm][3], smb + row*272 + kk*32 + lcolb);
            }
            #pragma unroll
            for (int n=0;n<8;n++){
                int nabs = wc*64 + n*8 + q;
                uint2 bb = *(const uint2*)(WB + nabs*64 + kk*8 + c4*2);
                MMA_BF16(c[0][n], a[0][0],a[0][1],a[0][2],a[0][3], bb.x, bb.y);
                MMA_BF16(c[1][n], a[1][0],a[1][1],a[1][2],a[1][3], bb.x, bb.y);
            }
        }

        if (nt == 0){
            #pragma unroll
            for (int mm=0;mm<2;mm++){
                int r1 = mbase + wr*32 + q + mm*16;
                #pragma unroll
                for (int n=0;n<8;n++){
                    int col = wc*64 + n*8 + 2*c4;
                    float2 y0 = { siluf(c[mm][n][0]), siluf(c[mm][n][1]) };
                    float2 y1 = { siluf(c[mm][n][2]), siluf(c[mm][n][3]) };
                    *(float2*)(g_gate + r1*128 + col)     = y0;
                    *(float2*)(g_gate + (r1+8)*128 + col) = y1;
                }
            }
        } else {
            unsigned short* oh = (nt==1) ? g_qwh : (nt==2 ? g_kwh : g_vwh);
            #pragma unroll
            for (int mm=0;mm<2;mm++){
                int r1 = mbase + wr*32 + q + mm*16;
                int dr1 = win_from_nat(r1);
                int dr2 = win_from_nat(r1+8);
                #pragma unroll
                for (int n=0;n<8;n++){
                    int col = wc*64 + n*8 + 2*c4;
                    __nv_bfloat162 h0 = __floats2bfloat162_rn(siluf(c[mm][n][0]), siluf(c[mm][n][1]));
                    __nv_bfloat162 h1 = __floats2bfloat162_rn(siluf(c[mm][n][2]), siluf(c[mm][n][3]));
                    *(__nv_bfloat162*)(oh + dr1*128 + col) = h0;
                    *(__nv_bfloat162*)(oh + dr2*128 + col) = h1;
                }
            }
        }
    }
}

// ======== K2a: per-chunk partial P, 144-row chunks (grid 256) ========
__global__ void __launch_bounds__(256)
k2a_mt(){
    extern __shared__ unsigned smw[];
    int tid = threadIdx.x, lane = tid & 31, w = tid >> 5;
    int q = lane >> 2, c4 = lane & 3;
    int cid = blockIdx.x;
    int batch = cid >> 6, r = cid & 63;
    int sl, ck;
    if (r < 16){ sl = 0; ck = r; }
    else if (r < 48){ sl = 1 + ((r-16)>>3); ck = (r-16)&7; }
    else { sl = 5 + ((r-48)>>2); ck = (r-48)&3; }
    int win = (sl==0)?0 : (sl<=2?1 : (sl<=4?2:3));
    int off = (sl==0)?0 : (sl==1?0 : (sl==2?1152 : (sl==3?0 : (sl==4?1152 : (sl-5)*576))));
    int grow = (batch*4 + win)*WL + off + ck*144;

    uint32_t smb = smem_u32(smw);
    const uint4* gk4 = (const uint4*)g_kwh;
    const uint4* gv4 = (const uint4*)g_vwh;

    float c[16][4];
    #pragma unroll
    for (int n=0;n<16;n++){ c[n][0]=0.f; c[n][1]=0.f; c[n][2]=0.f; c[n][3]=0.f; }
    float svacc = 0.f;

    uint32_t aOff = ((lane&7) + ((lane>>4)&1)*8)*272u + w*32u + ((lane>>3)&1)*16u;
    uint32_t bOff = ((lane&7) + ((lane>>3)&1)*8)*272u + ((lane>>4)&1)*16u;

    {
        int row = tid >> 4, q16 = tid & 15;
        CP16(smb + (KT0 + row*68 + q16*4)*4, (const void*)(gk4 + (grow + row)*16 + q16));
        CP16(smb + (VT0 + row*68 + q16*4)*4, (const void*)(gv4 + (grow + row)*16 + q16));
        CP_COMMIT;
    }
    CP_WAIT0;
    __syncthreads();

    const unsigned short* sp = (const unsigned short*)smw;

    for (int it=0; it<9; it++){
        int cK = (it&1) ? KT1 : KT0;
        int cV = (it&1) ? VT1 : VT0;
        int nK = (it&1) ? KT0 : KT1;
        int nV = (it&1) ? VT0 : VT1;
        if (it+1 < 9){
            int row = tid >> 4, q16 = tid & 15;
            int gr = grow + (it+1)*16 + row;
            CP16(smb + (nK + row*68 + q16*4)*4, (const void*)(gk4 + gr*16 + q16));
            CP16(smb + (nV + row*68 + q16*4)*4, (const void*)(gv4 + gr*16 + q16));
            CP_COMMIT;
        }
        unsigned a0,a1,a2,a3;
        LDM_X4T(a0,a1,a2,a3, smb + cV*4 + aOff);
        #pragma unroll
        for (int ng2=0; ng2<8; ng2++){
            unsigned b0,b1,b2,b3;
            LDM_X4T(b0,b1,b2,b3, smb + cK*4 + bOff + ng2*32);
            MMA_BF16(c[2*ng2],   a0,a1,a2,a3, b0,b1);
            MMA_BF16(c[2*ng2+1], a0,a1,a2,a3, b2,b3);
        }
        {
            int base = (tid < 128) ? (cK*2 + tid) : (cV*2 + (tid-128));
            #pragma unroll
            for (int rr=0; rr<16; rr++){
                unsigned short hv = sp[base + rr*136];
                svacc += __bfloat162float(*(__nv_bfloat16*)&hv);
            }
        }
        CP_WAIT0;
        __syncthreads();
    }

    unsigned* pb = g_Ppart + cid*8192;
    int d2a = w*16 + q, d2b = d2a + 8;
    #pragma unroll
    for (int ng=0; ng<16; ng++){
        int u = ng*4 + c4;
        PACK_BF2(pb[d2a*64 + u], c[ng][0], c[ng][1]);
        PACK_BF2(pb[d2b*64 + u], c[ng][2], c[ng][3]);
    }
    if (tid < 128) g_ksp[cid*128 + tid] = svacc;
    else           g_vsp[cid*128 + (tid-128)] = svacc;
}

// ============ K2c: reduce bf16 partials -> bf16 frag-ordered Mt (grid 36x8) ============
__global__ void k2c_reduce(){
    int s = blockIdx.x;
    int part = blockIdx.y;
    int batch = s / 9, sl = s - batch*9;
    int cb, nch;
    if (sl == 0){ cb = 0; nch = 16; }
    else if (sl < 5){ cb = 16 + (sl-1)*8; nch = 8; }
    else { cb = 48 + (sl-5)*4; nch = 4; }
    cb += batch*64;
    int tid = threadIdx.x;

    #pragma unroll
    for (int e=0; e<4; e++){
        int idx = part*1024 + tid + e*256;
        int n = idx >> 6, f = idx & 63;
        int kk = f >> 3, rr = f & 7;
        int c4v = rr >> 1, h = rr & 1;
        int u = kk*8 + h*4 + c4v;
        float s0 = 0.f, s1 = 0.f;
        #pragma unroll 4
        for (int cc=0; cc<nch; cc++){
            unsigned pv = g_Ppart[(cb+cc)*8192 + n*64 + u];
            __nv_bfloat162 hb = *(__nv_bfloat162*)&pv;
            s0 += __low2float(hb); s1 += __high2float(hb);
        }
        __nv_bfloat162 hh = __floats2bfloat162_rn(s0, s1);
        g_Mt[s*8192 + idx] = *(unsigned*)&hh;
    }
    if (part == 0){
        if (tid < 128){
            float a = 0.f;
            for (int cc=0; cc<nch; cc++) a += g_ksp[(cb+cc)*128 + tid];
            g_ksum[s*128 + tid] = a;
        } else {
            int t = tid - 128;
            float a = 0.f;
            for (int cc=0; cc<nch; cc++) a += g_vsp[(cb+cc)*128 + t];
            g_vsum[s*128 + t] = a;
        }
    }
}

// ============ K2b: O = (vsum + SCALE*Q@Mt)/l * gate, scatter natural bf16 ============
__global__ void __launch_bounds__(256)
k2b_qm(){
    int tid = threadIdx.x, lane = tid & 31, w = tid >> 5;
    int q = lane >> 2, c4 = lane & 3;
    int r0 = w*16 + q;
    int bx = blockIdx.x, batch = blockIdx.y;
    int sl, qt;
    if (bx < 18){ sl = 0; qt = bx; }
    else if (bx < 54){ int e = bx - 18; sl = 1 + e/9; qt = e - (sl-1)*9; }
    else { int e = bx - 54; sl = 5 + e/5; qt = e - (sl-5)*5; }
    int win = (sl==0)?0 : (sl<=2?1 : (sl<=4?2:3));
    int off = (sl==0)?0 : (sl==1?0 : (sl==2?1152 : (sl==3?0 : (sl==4?1152 : (sl-5)*576))));
    int len = (sl==0)?2304 : (sl<5?1152:576);
    int gsb = (batch*4 + win)*WL + off;

    int ra = qt*128 + r0;
    int rb = ra + 8;
    int va = ra < len, vb = rb < len;
    int rac = va ? ra : len-1;
    int rbc = vb ? rb : len-1;

    unsigned aq[8][4];
    {
        const unsigned* qp = (const unsigned*)g_qwh;
        int rA = (gsb + rac)*64, rB = (gsb + rbc)*64;
        #pragma unroll
        for (int kk=0;kk<8;kk++){
            aq[kk][0] = qp[rA + kk*8 + c4];
            aq[kk][1] = qp[rB + kk*8 + c4];
            aq[kk][2] = qp[rA + kk*8 + c4 + 4];
            aq[kk][3] = qp[rB + kk*8 + c4 + 4];
        }
    }

    const unsigned* MtS = g_Mt  + (batch*9 + sl)*8192;
    const float*    ksS = g_ksum + (batch*9 + sl)*128;
    const float*    vsS = g_vsum + (batch*9 + sl)*128;

    float c[16][4];
    #pragma unroll
    for (int n=0;n<16;n++){ c[n][0]=0.f; c[n][1]=0.f; c[n][2]=0.f; c[n][3]=0.f; }
    #pragma unroll
    for (int kk=0;kk<8;kk++){
        #pragma unroll
        for (int ng=0; ng<16; ng++){
            uint2 bb = *(const uint2*)(MtS + (ng*8+q)*64 + kk*8 + c4*2);
            MMA_BF16(c[ng], aq[kk][0],aq[kk][1],aq[kk][2],aq[kk][3], bb.x, bb.y);
        }
    }

    float d0 = 0.f, d1 = 0.f;
    #pragma unroll
    for (int kk=0;kk<8;kk++){
        #pragma unroll
        for (int h=0; h<2; h++){
            float2 ks2 = *(const float2*)(ksS + kk*16 + h*8 + 2*c4);
            unsigned ua = aq[kk][h*2], ub = aq[kk][h*2+1];
            __nv_bfloat162 ha = *(__nv_bfloat162*)&ua;
            __nv_bfloat162 hb = *(__nv_bfloat162*)&ub;
            d0 += __low2float(ha)*ks2.x + __high2float(ha)*ks2.y;
            d1 += __low2float(hb)*ks2.x + __high2float(hb)*ks2.y;
        }
    }
    d0 += __shfl_xor_sync(0xffffffffu, d0, 1);
    d0 += __shfl_xor_sync(0xffffffffu, d0, 2);
    d1 += __shfl_xor_sync(0xffffffffu, d1, 1);
    d1 += __shfl_xor_sync(0xffffffffu, d1, 2);
    float inv0 = __fdividef(1.f, (float)len + SCALE_S*d0);
    float inv1 = __fdividef(1.f, (float)len + SCALE_S*d1);

    int natr0 = va ? nat_from_reg(batch, win, off + ra) : 0;
    int natr1 = vb ? nat_from_reg(batch, win, off + rb) : 0;

    #pragma unroll
    for (int ng=0; ng<16; ng++){
        int col = ng*8 + 2*c4;
        float2 vs2 = *(const float2*)(vsS + col);
        if (va){
            float2 g2 = *(const float2*)(g_gate + natr0*128 + col);
            float ox = (vs2.x + SCALE_S*c[ng][0])*inv0*g2.x;
            float oy = (vs2.y + SCALE_S*c[ng][1])*inv0*g2.y;
            __nv_bfloat162 hh = __floats2bfloat162_rn(ox, oy);
            g_atth[natr0*64 + ng*4 + c4] = *(unsigned*)&hh;
        }
        if (vb){
            float2 g2 = *(const float2*)(g_gate + natr1*128 + col);
            float ox = (vs2.x + SCALE_S*c[ng][2])*inv1*g2.x;
            float oy = (vs2.y + SCALE_S*c[ng][3])*inv1*g2.y;
            __nv_bfloat162 hh = __floats2bfloat162_rn(ox, oy);
            g_atth[natr1*64 + ng*4 + c4] = *(unsigned*)&hh;
        }
    }
}

// ====== K3: bf16 silu(X@W1+b1)@W2 + residual (R12/R9 version) ======
__global__ void __launch_bounds__(256)
out_kernel(const float* __restrict__ b1, const float* __restrict__ src,
           float* __restrict__ outp, int copies){
    extern __shared__ unsigned smu[];
    unsigned* Ah = smu;
    unsigned* Xs = smu + OU_XS3;
    int tid = threadIdx.x, lane = tid & 31, w = tid >> 5;
    int q = lane >> 2, c4 = lane & 3;
    int wr = w >> 1, wc = w & 1;
    int mbase = blockIdx.x * 128;
    uint32_t smbA = smem_u32(Ah);
    uint32_t smbX = smem_u32(Xs);

    #pragma unroll
    for (int it=0; it<16; it++){
        int idx = tid + it*256; int row = idx>>5, cq = idx&31;
        uint2 v = ((const uint2*)g_atth)[(size_t)(mbase+row)*32 + cq];
        *(uint2*)&Ah[row*68 + cq*2] = v;
    }
    __syncthreads();

    int lrow = (lane&7) + ((lane>>3)&1)*8;
    int lcolb = ((lane>>4)&1)*16;

    const unsigned* WB1 = g_wprep + 32768;
    float c[2][8][4];
    #pragma unroll
    for (int n=0;n<8;n++){
        int col = wc*64 + n*8 + 2*c4;
        float bb0 = b1[col], bb1v = b1[col+1];
        c[0][n][0]=bb0; c[0][n][1]=bb1v; c[0][n][2]=bb0; c[0][n][3]=bb1v;
        c[1][n][0]=bb0; c[1][n][1]=bb1v; c[1][n][2]=bb0; c[1][n][3]=bb1v;
    }
    #pragma unroll
    for (int kk=0;kk<8;kk++){
        unsigned a[2][4];
        #pragma unroll
        for (int mm=0;mm<2;mm++){
            int row = wr*32 + mm*16 + lrow;
            LDM_X4(a[mm][0],a[mm][1],a[mm][2],a[mm][3], smbA + row*272 + kk*32 + lcolb);
        }
        #pragma unroll
        for (int n=0;n<8;n++){
            int nabs = wc*64 + n*8 + q;
            uint2 bb = *(const uint2*)(WB1 + nabs*64 + kk*8 + c4*2);
            MMA_BF16(c[0][n], a[0][0],a[0][1],a[0][2],a[0][3], bb.x, bb.y);
            MMA_BF16(c[1][n], a[1][0],a[1][1],a[1][2],a[1][3], bb.x, bb.y);
        }
    }
    #pragma unroll
    for (int mm=0;mm<2;mm++){
        int r1 = wr*32 + q + mm*16;
        #pragma unroll
        for (int n=0;n<8;n++){
            int ci = wc*32 + n*4 + c4;
            __nv_bfloat162 h0 = __floats2bfloat162_rn(siluf(c[mm][n][0]), siluf(c[mm][n][1]));
            __nv_bfloat162 h1 = __floats2bfloat162_rn(siluf(c[mm][n][2]), siluf(c[mm][n][3]));
            Xs[r1*68 + ci]     = *(unsigned*)&h0;
            Xs[(r1+8)*68 + ci] = *(unsigned*)&h1;
        }
    }
    __syncthreads();

    const unsigned* WB2 = g_wprep + 40960;
    float c2[2][8][4];
    #pragma unroll
    for (int mm=0;mm<2;mm++)
        #pragma unroll
        for (int n=0;n<8;n++){ c2[mm][n][0]=0.f; c2[mm][n][1]=0.f; c2[mm][n][2]=0.f; c2[mm][n][3]=0.f; }
    #pragma unroll
    for (int kk=0;kk<8;kk++){
        unsigned a[2][4];
        #pragma unroll
        for (int mm=0;mm<2;mm++){
            int row = wr*32 + mm*16 + lrow;
            LDM_X4(a[mm][0],a[mm][1],a[mm][2],a[mm][3], smbX + row*272 + kk*32 + lcolb);
        }
        #pragma unroll
        for (int n=0;n<8;n++){
            int nabs = wc*64 + n*8 + q;
            uint2 bb = *(const uint2*)(WB2 + nabs*64 + kk*8 + c4*2);
            MMA_BF16(c2[0][n], a[0][0],a[0][1],a[0][2],a[0][3], bb.x, bb.y);
            MMA_BF16(c2[1][n], a[1][0],a[1][1],a[1][2],a[1][3], bb.x, bb.y);
        }
    }
    #pragma unroll
    for (int mm=0;mm<2;mm++){
        int r1 = mbase + wr*32 + q + mm*16;
        #pragma unroll
        for (int n=0;n<8;n++){
            int col = wc*64 + n*8 + 2*c4;
            float2 s0 = *(const float2*)(src + r1*128 + col);
            float2 s1 = *(const float2*)(src + (r1+8)*128 + col);
            float2 y0 = { c2[mm][n][0] + s0.x, c2[mm][n][1] + s0.y };
            float2 y1 = { c2[mm][n][2] + s1.x, c2[mm][n][3] + s1.y };
            for (int cp=0; cp<copies; cp++){
                *(float2*)(outp + (size_t)cp*ROWS_T*128 + r1*128 + col)     = y0;
                *(float2*)(outp + (size_t)cp*ROWS_T*128 + (r1+8)*128 + col) = y1;
            }
        }
    }
}

extern "C" void kernel_launch(void* const* d_in, const int* in_sizes, int n_in,
                              void* d_out, int out_size){
    int o = (n_in >= 14 && in_sizes[3] == 1) ? 2 : 0;
    const float* source = (const float*)d_in[0];
    const float* ln_g   = (const float*)d_in[3+o];
    const float* ln_b   = (const float*)d_in[4+o];
    const float* w_gq   = (const float*)d_in[5+o];
    const float* b_gq   = (const float*)d_in[6+o];
    const float* w_kv   = (const float*)d_in[7+o];
    const float* b_kv   = (const float*)d_in[8+o];
    const float* w_o1   = (const float*)d_in[9+o];
    const float* b_o1   = (const float*)d_in[10+o];
    const float* w_o2   = (const float*)d_in[11+o];
    int copies = out_size / (ROWS_T*128);
    if (copies < 1) copies = 1;

    static int attr_done = 0;
    if (!attr_done){
        cudaFuncSetAttribute(proj_fused, cudaFuncAttributeMaxDynamicSharedMemorySize, PROJ_SMEM3);
        cudaFuncSetAttribute(k2a_mt,     cudaFuncAttributeMaxDynamicSharedMemorySize, K2A_SMEM);
        cudaFuncSetAttribute(out_kernel, cudaFuncAttributeMaxDynamicSharedMemorySize, OUT_SMEM3);
        attr_done = 1;
    }

    prep_w<<<192, 256>>>(w_gq, w_kv, w_o1, w_o2);
    proj_fused<<<ROWS_T/128, 256, PROJ_SMEM3>>>(source, ln_g, ln_b, b_gq, b_kv);
    k2a_mt<<<256, 256, K2A_SMEM>>>();
    k2c_reduce<<<dim3(36, 8), 256>>>();
    k2b_qm<<<dim3(74, 4), 256>>>();
    out_kernel<<<ROWS_T/128, 256, OUT_SMEM3>>>(b_o1, source, (float*)d_out, copies);
}

// round 16
// speedup vs baseline: 1.1693x; 1.0184x over previous
#include <cuda_runtime.h>
#include <cuda_bf16.h>
#include <cstdint>

#define ROWS_T 36864
#define SEQ    9216
#define WL     2304
#define SCALE_S (1.0f/1179648.0f)

#define PJ_S32 8704
#define PROJ_SMEM3 ((8704 + 16896)*4)
#define OU_XS3 8704
#define OUT_SMEM3 ((8704 + 8704)*4)
#define KT0 0
#define VT0 1088
#define KT1 2176
#define VT1 3264
#define K2A_SMEM (4352*4)

__device__ unsigned g_gateh[ROWS_T*64];   // bf16-pair gate, natural layout
__device__ unsigned short g_qwh[ROWS_T*128];
__device__ unsigned short g_kwh[ROWS_T*128];
__device__ unsigned short g_vwh[ROWS_T*128];
__device__ unsigned g_wprep[49152];
__device__ unsigned g_Ppart[256*8192];
__device__ float g_ksp[256*128];
__device__ float g_vsp[256*128];
__device__ unsigned g_Mt[36*8192];
__device__ float g_ksum[36*128];
__device__ float g_vsum[36*128];
__device__ unsigned g_atth[ROWS_T*64];

__device__ __forceinline__ float siluf(float x){ return x / (1.0f + __expf(-x)); }

__device__ __forceinline__ int win_from_nat(int r){
    int b = r / SEQ; int p = r - b*SEQ;
    int y = p / 96, x = p - y*96;
    int yr = y + 72; if (yr >= 96) yr -= 96;
    int xr = x + 72; if (xr >= 96) xr -= 96;
    int wy = yr / 48, iy = yr - wy*48;
    int wx = xr / 48, ix = xr - wx*48;
    int w = wy*2 + wx;
    int j;
    if (w == 0)      j = iy*48 + ix;
    else if (w == 1){ int sx = ix >= 24; j = sx*1152 + iy*24 + (ix - sx*24); }
    else if (w == 2){ int sy = iy >= 24; j = sy*1152 + (iy - sy*24)*48 + ix; }
    else { int sy = iy >= 24, sx = ix >= 24;
           j = (sy*2+sx)*576 + (iy - sy*24)*24 + (ix - sx*24); }
    return (b*4 + w)*WL + j;
}
__device__ __forceinline__ int nat_from_reg(int batch, int wv, int wrem){
    int wy = wv >> 1, wx = wv & 1;
    int iy, ix;
    if (wv == 0){ iy = wrem/48; ix = wrem - iy*48; }
    else if (wv == 1){ int sx = wrem >= 1152; int t = wrem - sx*1152; iy = t/24; ix = sx*24 + (t - iy*24); }
    else if (wv == 2){ int sy = wrem >= 1152; int t = wrem - sy*1152; int r = t/48; iy = sy*24 + r; ix = t - r*48; }
    else { int sg = wrem/576; int t = wrem - sg*576; int sy = sg>>1, sx = sg&1;
           int r = t/24; iy = sy*24 + r; ix = sx*24 + (t - r*24); }
    int y = wy*48 + iy + 24; if (y >= 96) y -= 96;
    int x = wx*48 + ix + 24; if (x >= 96) x -= 96;
    return batch*SEQ + y*96 + x;
}

__device__ __forceinline__ uint32_t smem_u32(const void* p){
    uint32_t a;
    asm("{ .reg .u64 t; cvta.to.shared.u64 t, %1; cvt.u32.u64 %0, t; }" : "=r"(a) : "l"(p));
    return a;
}

#define MMA_BF16(c, a0,a1,a2,a3, b0,b1) \
    asm volatile("mma.sync.aligned.m16n8k16.row.col.f32.bf16.bf16.f32 " \
        "{%0,%1,%2,%3},{%4,%5,%6,%7},{%8,%9},{%0,%1,%2,%3};" \
        : "+f"((c)[0]),"+f"((c)[1]),"+f"((c)[2]),"+f"((c)[3]) \
        : "r"(a0),"r"(a1),"r"(a2),"r"(a3),"r"(b0),"r"(b1))

#define LDM_X4(b0,b1,b2,b3,addr) \
    asm volatile("ldmatrix.sync.aligned.m8n8.x4.shared.b16 {%0,%1,%2,%3}, [%4];" \
        : "=r"(b0),"=r"(b1),"=r"(b2),"=r"(b3) : "r"(addr))
#define LDM_X4T(b0,b1,b2,b3,addr) \
    asm volatile("ldmatrix.sync.aligned.m8n8.x4.trans.shared.b16 {%0,%1,%2,%3}, [%4];" \
        : "=r"(b0),"=r"(b1),"=r"(b2),"=r"(b3) : "r"(addr))

#define CP16(dst, src) \
    asm volatile("cp.async.cg.shared.global [%0], [%1], 16;" :: "r"(dst), "l"(src))
#define CP_COMMIT asm volatile("cp.async.commit_group;")
#define CP_WAIT0  asm volatile("cp.async.wait_group 0;")

#define PACK_BF2(u, x, y) do { __nv_bfloat162 _h = __floats2bfloat162_rn((x),(y)); (u) = *(unsigned*)&_h; } while(0)

// ============ K0: weight prep ============
__global__ void prep_w(const float* __restrict__ gq, const float* __restrict__ kv,
                       const float* __restrict__ o1, const float* __restrict__ o2){
    int id = blockIdx.x*256 + threadIdx.x;
    const float* W; int rem, ncols;
    if (id < 32768){ W = (id < 16384) ? gq : kv; ncols = 256; rem = id & 16383; }
    else           { W = (id < 40960) ? o1 : o2; ncols = 128; rem = id & 8191; }
    int n  = rem >> 6;
    int r  = rem & 63;
    int kk = r >> 3, c4 = (r >> 1) & 3, h = r & 1;
    int k0 = kk*16 + h*8 + 2*c4;
    __nv_bfloat162 hh = __floats2bfloat162_rn(W[k0*ncols + n], W[(k0+1)*ncols + n]);
    g_wprep[id] = *(unsigned*)&hh;
}

// ============ K1: fused LN + (gate,Q,K,V) bf16 projection ============
__global__ void __launch_bounds__(256)
proj_fused(const float* __restrict__ src, const float* __restrict__ lg, const float* __restrict__ lb,
           const float* __restrict__ b_gq, const float* __restrict__ b_kv){
    extern __shared__ unsigned smu[];
    float* S32 = (float*)(smu + PJ_S32);
    int tid = threadIdx.x, lane = tid & 31, w = tid >> 5;
    int q = lane >> 2, c4 = lane & 3;
    int wr = w >> 1, wc = w & 1;
    int mbase = blockIdx.x * 128;
    uint32_t smb = smem_u32(smu);

    const float4* Sg = ((const float4*)src) + mbase*32;
    #pragma unroll
    for (int it=0; it<16; it++){
        int idx = tid + it*256; int row = idx>>5, cq = idx&31;
        *(float4*)&S32[row*132 + cq*4] = Sg[idx];
    }
    __syncthreads();
    if (tid < 128){
        float s=0.f, s2=0.f;
        #pragma unroll
        for (int i=0;i<32;i++){
            float4 v = *(float4*)&S32[tid*132 + i*4];
            s += v.x+v.y+v.z+v.w;
            s2 += v.x*v.x+v.y*v.y+v.z*v.z+v.w*v.w;
        }
        float mean = s*(1.f/128.f);
        float var  = s2*(1.f/128.f) - mean*mean;
        float rs   = rsqrtf(var + 1e-5f);
        #pragma unroll
        for (int i=0;i<32;i++){
            float4 v = *(float4*)&S32[tid*132 + i*4];
            float4 g4 = ((const float4*)lg)[i];
            float4 b4 = ((const float4*)lb)[i];
            float x0 = (v.x-mean)*rs*g4.x + b4.x;
            float x1 = (v.y-mean)*rs*g4.y + b4.y;
            float x2 = (v.z-mean)*rs*g4.z + b4.z;
            float x3 = (v.w-mean)*rs*g4.w + b4.w;
            __nv_bfloat162 h0 = __floats2bfloat162_rn(x0, x1);
            __nv_bfloat162 h1 = __floats2bfloat162_rn(x2, x3);
            uint2 u; u.x = *(unsigned*)&h0; u.y = *(unsigned*)&h1;
            *(uint2*)&smu[tid*68 + i*2] = u;
        }
    }
    __syncthreads();

    int lrow = (lane&7) + ((lane>>3)&1)*8;
    int lcolb = ((lane>>4)&1)*16;

    for (int nt=0; nt<4; nt++){
        const unsigned* WB = g_wprep + nt*8192;
        const float* bias  = (nt<2) ? (b_gq + nt*128) : (b_kv + (nt-2)*128);

        float c[2][8][4];
        #pragma unroll
        for (int n=0;n<8;n++){
            int col = wc*64 + n*8 + 2*c4;
            float bb0 = bias[col], bb1 = bias[col+1];
            c[0][n][0]=bb0; c[0][n][1]=bb1; c[0][n][2]=bb0; c[0][n][3]=bb1;
            c[1][n][0]=bb0; c[1][n][1]=bb1; c[1][n][2]=bb0; c[1][n][3]=bb1;
        }
        #pragma unroll
        for (int kk=0;kk<8;kk++){
            unsigned a[2][4];
            #pragma unroll
            for (int mm=0;mm<2;mm++){
                int row = wr*32 + mm*16 + lrow;
                LDM_X4(a[mm][0],a[mm][1],a[mm][2],a[mm][3], smb + row*272 + kk*32 + lcolb);
            }
            #pragma unroll
            for (int n=0;n<8;n++){
                int nabs = wc*64 + n*8 + q;
                uint2 bb = *(const uint2*)(WB + nabs*64 + kk*8 + c4*2);
                MMA_BF16(c[0][n], a[0][0],a[0][1],a[0][2],a[0][3], bb.x, bb.y);
                MMA_BF16(c[1][n], a[1][0],a[1][1],a[1][2],a[1][3], bb.x, bb.y);
            }
        }

        if (nt == 0){
            #pragma unroll
            for (int mm=0;mm<2;mm++){
                int r1 = mbase + wr*32 + q + mm*16;
                #pragma unroll
                for (int n=0;n<8;n++){
                    int ci = wc*32 + n*4 + c4;
                    unsigned u0, u1;
                    PACK_BF2(u0, siluf(c[mm][n][0]), siluf(c[mm][n][1]));
                    PACK_BF2(u1, siluf(c[mm][n][2]), siluf(c[mm][n][3]));
                    g_gateh[r1*64 + ci]     = u0;
                    g_gateh[(r1+8)*64 + ci] = u1;
                }
            }
        } else {
            unsigned short* oh = (nt==1) ? g_qwh : (nt==2 ? g_kwh : g_vwh);
            #pragma unroll
            for (int mm=0;mm<2;mm++){
                int r1 = mbase + wr*32 + q + mm*16;
                int dr1 = win_from_nat(r1);
                int dr2 = win_from_nat(r1+8);
                #pragma unroll
                for (int n=0;n<8;n++){
                    int col = wc*64 + n*8 + 2*c4;
                    __nv_bfloat162 h0 = __floats2bfloat162_rn(siluf(c[mm][n][0]), siluf(c[mm][n][1]));
                    __nv_bfloat162 h1 = __floats2bfloat162_rn(siluf(c[mm][n][2]), siluf(c[mm][n][3]));
                    *(__nv_bfloat162*)(oh + dr1*128 + col) = h0;
                    *(__nv_bfloat162*)(oh + dr2*128 + col) = h1;
                }
            }
        }
    }
}

// ======== K2a: per-chunk partial P, 144-row chunks (grid 256) ========
__global__ void __launch_bounds__(256)
k2a_mt(){
    extern __shared__ unsigned smw[];
    int tid = threadIdx.x, lane = tid & 31, w = tid >> 5;
    int q = lane >> 2, c4 = lane & 3;
    int cid = blockIdx.x;
    int batch = cid >> 6, r = cid & 63;
    int sl, ck;
    if (r < 16){ sl = 0; ck = r; }
    else if (r < 48){ sl = 1 + ((r-16)>>3); ck = (r-16)&7; }
    else { sl = 5 + ((r-48)>>2); ck = (r-48)&3; }
    int win = (sl==0)?0 : (sl<=2?1 : (sl<=4?2:3));
    int off = (sl==0)?0 : (sl==1?0 : (sl==2?1152 : (sl==3?0 : (sl==4?1152 : (sl-5)*576))));
    int grow = (batch*4 + win)*WL + off + ck*144;

    uint32_t smb = smem_u32(smw);
    const uint4* gk4 = (const uint4*)g_kwh;
    const uint4* gv4 = (const uint4*)g_vwh;

    float c[16][4];
    #pragma unroll
    for (int n=0;n<16;n++){ c[n][0]=0.f; c[n][1]=0.f; c[n][2]=0.f; c[n][3]=0.f; }
    float svacc = 0.f;

    uint32_t aOff = ((lane&7) + ((lane>>4)&1)*8)*272u + w*32u + ((lane>>3)&1)*16u;
    uint32_t bOff = ((lane&7) + ((lane>>3)&1)*8)*272u + ((lane>>4)&1)*16u;

    {
        int row = tid >> 4, q16 = tid & 15;
        CP16(smb + (KT0 + row*68 + q16*4)*4, (const void*)(gk4 + (grow + row)*16 + q16));
        CP16(smb + (VT0 + row*68 + q16*4)*4, (const void*)(gv4 + (grow + row)*16 + q16));
        CP_COMMIT;
    }
    CP_WAIT0;
    __syncthreads();

    const unsigned short* sp = (const unsigned short*)smw;

    for (int it=0; it<9; it++){
        int cK = (it&1) ? KT1 : KT0;
        int cV = (it&1) ? VT1 : VT0;
        int nK = (it&1) ? KT0 : KT1;
        int nV = (it&1) ? VT0 : VT1;
        if (it+1 < 9){
            int row = tid >> 4, q16 = tid & 15;
            int gr = grow + (it+1)*16 + row;
            CP16(smb + (nK + row*68 + q16*4)*4, (const void*)(gk4 + gr*16 + q16));
            CP16(smb + (nV + row*68 + q16*4)*4, (const void*)(gv4 + gr*16 + q16));
            CP_COMMIT;
        }
        unsigned a0,a1,a2,a3;
        LDM_X4T(a0,a1,a2,a3, smb + cV*4 + aOff);
        #pragma unroll
        for (int ng2=0; ng2<8; ng2++){
            unsigned b0,b1,b2,b3;
            LDM_X4T(b0,b1,b2,b3, smb + cK*4 + bOff + ng2*32);
            MMA_BF16(c[2*ng2],   a0,a1,a2,a3, b0,b1);
            MMA_BF16(c[2*ng2+1], a0,a1,a2,a3, b2,b3);
        }
        {
            int base = (tid < 128) ? (cK*2 + tid) : (cV*2 + (tid-128));
            #pragma unroll
            for (int rr=0; rr<16; rr++){
                unsigned short hv = sp[base + rr*136];
                svacc += __bfloat162float(*(__nv_bfloat16*)&hv);
            }
        }
        CP_WAIT0;
        __syncthreads();
    }

    unsigned* pb = g_Ppart + cid*8192;
    int d2a = w*16 + q, d2b = d2a + 8;
    #pragma unroll
    for (int ng=0; ng<16; ng++){
        int u = ng*4 + c4;
        PACK_BF2(pb[d2a*64 + u], c[ng][0], c[ng][1]);
        PACK_BF2(pb[d2b*64 + u], c[ng][2], c[ng][3]);
    }
    if (tid < 128) g_ksp[cid*128 + tid] = svacc;
    else           g_vsp[cid*128 + (tid-128)] = svacc;
}

// ============ K2c: reduce bf16 partials -> bf16 frag-ordered Mt (grid 36x8) ============
__global__ void k2c_reduce(){
    int s = blockIdx.x;
    int part = blockIdx.y;
    int batch = s / 9, sl = s - batch*9;
    int cb, nch;
    if (sl == 0){ cb = 0; nch = 16; }
    else if (sl < 5){ cb = 16 + (sl-1)*8; nch = 8; }
    else { cb = 48 + (sl-5)*4; nch = 4; }
    cb += batch*64;
    int tid = threadIdx.x;

    #pragma unroll
    for (int e=0; e<4; e++){
        int idx = part*1024 + tid + e*256;
        int n = idx >> 6, f = idx & 63;
        int kk = f >> 3, rr = f & 7;
        int c4v = rr >> 1, h = rr & 1;
        int u = kk*8 + h*4 + c4v;
        float s0 = 0.f, s1 = 0.f;
        #pragma unroll 4
        for (int cc=0; cc<nch; cc++){
            unsigned pv = g_Ppart[(cb+cc)*8192 + n*64 + u];
            __nv_bfloat162 hb = *(__nv_bfloat162*)&pv;
            s0 += __low2float(hb); s1 += __high2float(hb);
        }
        __nv_bfloat162 hh = __floats2bfloat162_rn(s0, s1);
        g_Mt[s*8192 + idx] = *(unsigned*)&hh;
    }
    if (part == 0){
        if (tid < 128){
            float a = 0.f;
            for (int cc=0; cc<nch; cc++) a += g_ksp[(cb+cc)*128 + tid];
            g_ksum[s*128 + tid] = a;
        } else {
            int t = tid - 128;
            float a = 0.f;
            for (int cc=0; cc<nch; cc++) a += g_vsp[(cb+cc)*128 + t];
            g_vsum[s*128 + t] = a;
        }
    }
}

// ============ K2b: O = (vsum + SCALE*Q@Mt)/l * gate, scatter natural bf16 ============
__global__ void __launch_bounds__(256)
k2b_qm(){
    int tid = threadIdx.x, lane = tid & 31, w = tid >> 5;
    int q = lane >> 2, c4 = lane & 3;
    int r0 = w*16 + q;
    int bx = blockIdx.x, batch = blockIdx.y;
    int sl, qt;
    if (bx < 18){ sl = 0; qt = bx; }
    else if (bx < 54){ int e = bx - 18; sl = 1 + e/9; qt = e - (sl-1)*9; }
    else { int e = bx - 54; sl = 5 + e/5; qt = e - (sl-5)*5; }
    int win = (sl==0)?0 : (sl<=2?1 : (sl<=4?2:3));
    int off = (sl==0)?0 : (sl==1?0 : (sl==2?1152 : (sl==3?0 : (sl==4?1152 : (sl-5)*576))));
    int len = (sl==0)?2304 : (sl<5?1152:576);
    int gsb = (batch*4 + win)*WL + off;

    int ra = qt*128 + r0;
    int rb = ra + 8;
    int va = ra < len, vb = rb < len;
    int rac = va ? ra : len-1;
    int rbc = vb ? rb : len-1;

    unsigned aq[8][4];
    {
        const unsigned* qp = (const unsigned*)g_qwh;
        int rA = (gsb + rac)*64, rB = (gsb + rbc)*64;
        #pragma unroll
        for (int kk=0;kk<8;kk++){
            aq[kk][0] = qp[rA + kk*8 + c4];
            aq[kk][1] = qp[rB + kk*8 + c4];
            aq[kk][2] = qp[rA + kk*8 + c4 + 4];
            aq[kk][3] = qp[rB + kk*8 + c4 + 4];
        }
    }

    const unsigned* MtS = g_Mt  + (batch*9 + sl)*8192;
    const float*    ksS = g_ksum + (batch*9 + sl)*128;
    const float*    vsS = g_vsum + (batch*9 + sl)*128;

    float c[16][4];
    #pragma unroll
    for (int n=0;n<16;n++){ c[n][0]=0.f; c[n][1]=0.f; c[n][2]=0.f; c[n][3]=0.f; }
    #pragma unroll
    for (int kk=0;kk<8;kk++){
        #pragma unroll
        for (int ng=0; ng<16; ng++){
            uint2 bb = *(const uint2*)(MtS + (ng*8+q)*64 + kk*8 + c4*2);
            MMA_BF16(c[ng], aq[kk][0],aq[kk][1],aq[kk][2],aq[kk][3], bb.x, bb.y);
        }
    }

    float d0 = 0.f, d1 = 0.f;
    #pragma unroll
    for (int kk=0;kk<8;kk++){
        #pragma unroll
        for (int h=0; h<2; h++){
            float2 ks2 = *(const float2*)(ksS + kk*16 + h*8 + 2*c4);
            unsigned ua = aq[kk][h*2], ub = aq[kk][h*2+1];
            __nv_bfloat162 ha = *(__nv_bfloat162*)&ua;
            __nv_bfloat162 hb = *(__nv_bfloat162*)&ub;
            d0 += __low2float(ha)*ks2.x + __high2float(ha)*ks2.y;
            d1 += __low2float(hb)*ks2.x + __high2float(hb)*ks2.y;
        }
    }
    d0 += __shfl_xor_sync(0xffffffffu, d0, 1);
    d0 += __shfl_xor_sync(0xffffffffu, d0, 2);
    d1 += __shfl_xor_sync(0xffffffffu, d1, 1);
    d1 += __shfl_xor_sync(0xffffffffu, d1, 2);
    float inv0 = __fdividef(1.f, (float)len + SCALE_S*d0);
    float inv1 = __fdividef(1.f, (float)len + SCALE_S*d1);

    int natr0 = va ? nat_from_reg(batch, win, off + ra) : 0;
    int natr1 = vb ? nat_from_reg(batch, win, off + rb) : 0;

    #pragma unroll
    for (int ng=0; ng<16; ng++){
        int col = ng*8 + 2*c4;
        float2 vs2 = *(const float2*)(vsS + col);
        if (va){
            unsigned gu = g_gateh[natr0*64 + ng*4 + c4];
            __nv_bfloat162 gh = *(__nv_bfloat162*)&gu;
            float ox = (vs2.x + SCALE_S*c[ng][0])*inv0*__low2float(gh);
            float oy = (vs2.y + SCALE_S*c[ng][1])*inv0*__high2float(gh);
            __nv_bfloat162 hh = __floats2bfloat162_rn(ox, oy);
            g_atth[natr0*64 + ng*4 + c4] = *(unsigned*)&hh;
        }
        if (vb){
            unsigned gu = g_gateh[natr1*64 + ng*4 + c4];
            __nv_bfloat162 gh = *(__nv_bfloat162*)&gu;
            float ox = (vs2.x + SCALE_S*c[ng][2])*inv1*__low2float(gh);
            float oy = (vs2.y + SCALE_S*c[ng][3])*inv1*__high2float(gh);
            __nv_bfloat162 hh = __floats2bfloat162_rn(ox, oy);
            g_atth[natr1*64 + ng*4 + c4] = *(unsigned*)&hh;
        }
    }
}

// ====== K3: bf16 silu(X@W1+b1)@W2 + residual ======
__global__ void __launch_bounds__(256)
out_kernel(const float* __restrict__ b1, const float* __restrict__ src,
           float* __restrict__ outp, int copies){
    extern __shared__ unsigned smu[];
    unsigned* Ah = smu;
    unsigned* Xs = smu + OU_XS3;
    int tid = threadIdx.x, lane = tid & 31, w = tid >> 5;
    int q = lane >> 2, c4 = lane & 3;
    int wr = w >> 1, wc = w & 1;
    int mbase = blockIdx.x * 128;
    uint32_t smbA = smem_u32(Ah);
    uint32_t smbX = smem_u32(Xs);

    #pragma unroll
    for (int it=0; it<16; it++){
        int idx = tid + it*256; int row = idx>>5, cq = idx&31;
        uint2 v = ((const uint2*)g_atth)[(size_t)(mbase+row)*32 + cq];
        *(uint2*)&Ah[row*68 + cq*2] = v;
    }
    __syncthreads();

    int lrow = (lane&7) + ((lane>>3)&1)*8;
    int lcolb = ((lane>>4)&1)*16;

    const unsigned* WB1 = g_wprep + 32768;
    float c[2][8][4];
    #pragma unroll
    for (int n=0;n<8;n++){
        int col = wc*64 + n*8 + 2*c4;
        float bb0 = b1[col], bb1v = b1[col+1];
        c[0][n][0]=bb0; c[0][n][1]=bb1v; c[0][n][2]=bb0; c[0][n][3]=bb1v;
        c[1][n][0]=bb0; c[1][n][1]=bb1v; c[1][n][2]=bb0; c[1][n][3]=bb1v;
    }
    #pragma unroll
    for (int kk=0;kk<8;kk++){
        unsigned a[2][4];
        #pragma unroll
        for (int mm=0;mm<2;mm++){
            int row = wr*32 + mm*16 + lrow;
            LDM_X4(a[mm][0],a[mm][1],a[mm][2],a[mm][3], smbA + row*272 + kk*32 + lcolb);
        }
        #pragma unroll
        for (int n=0;n<8;n++){
            int nabs = wc*64 + n*8 + q;
            uint2 bb = *(const uint2*)(WB1 + nabs*64 + kk*8 + c4*2);
            MMA_BF16(c[0][n], a[0][0],a[0][1],a[0][2],a[0][3], bb.x, bb.y);
            MMA_BF16(c[1][n], a[1][0],a[1][1],a[1][2],a[1][3], bb.x, bb.y);
        }
    }
    #pragma unroll
    for (int mm=0;mm<2;mm++){
        int r1 = wr*32 + q + mm*16;
        #pragma unroll
        for (int n=0;n<8;n++){
            int ci = wc*32 + n*4 + c4;
            __nv_bfloat162 h0 = __floats2bfloat162_rn(siluf(c[mm][n][0]), siluf(c[mm][n][1]));
            __nv_bfloat162 h1 = __floats2bfloat162_rn(siluf(c[mm][n][2]), siluf(c[mm][n][3]));
            Xs[r1*68 + ci]     = *(unsigned*)&h0;
            Xs[(r1+8)*68 + ci] = *(unsigned*)&h1;
        }
    }
    __syncthreads();

    const unsigned* WB2 = g_wprep + 40960;
    float c2[2][8][4];
    #pragma unroll
    for (int mm=0;mm<2;mm++)
        #pragma unroll
        for (int n=0;n<8;n++){ c2[mm][n][0]=0.f; c2[mm][n][1]=0.f; c2[mm][n][2]=0.f; c2[mm][n][3]=0.f; }
    #pragma unroll
    for (int kk=0;kk<8;kk++){
        unsigned a[2][4];
        #pragma unroll
        for (int mm=0;mm<2;mm++){
            int row = wr*32 + mm*16 + lrow;
            LDM_X4(a[mm][0],a[mm][1],a[mm][2],a[mm][3], smbX + row*272 + kk*32 + lcolb);
        }
        #pragma unroll
        for (int n=0;n<8;n++){
            int nabs = wc*64 + n*8 + q;
            uint2 bb = *(const uint2*)(WB2 + nabs*64 + kk*8 + c4*2);
            MMA_BF16(c2[0][n], a[0][0],a[0][1],a[0][2],a[0][3], bb.x, bb.y);
            MMA_BF16(c2[1][n], a[1][0],a[1][1],a[1][2],a[1][3], bb.x, bb.y);
        }
    }
    #pragma unroll
    for (int mm=0;mm<2;mm++){
        int r1 = mbase + wr*32 + q + mm*16;
        #pragma unroll
        for (int n=0;n<8;n++){
            int col = wc*64 + n*8 + 2*c4;
            float2 s0 = *(const float2*)(src + r1*128 + col);
            float2 s1 = *(const float2*)(src + (r1+8)*128 + col);
            float2 y0 = { c2[mm][n][0] + s0.x, c2[mm][n][1] + s0.y };
            float2 y1 = { c2[mm][n][2] + s1.x, c2[mm][n][3] + s1.y };
            for (int cp=0; cp<copies; cp++){
                *(float2*)(outp + (size_t)cp*ROWS_T*128 + r1*128 + col)     = y0;
                *(float2*)(outp + (size_t)cp*ROWS_T*128 + (r1+8)*128 + col) = y1;
            }
        }
    }
}

extern "C" void kernel_launch(void* const* d_in, const int* in_sizes, int n_in,
                              void* d_out, int out_size){
    int o = (n_in >= 14 && in_sizes[3] == 1) ? 2 : 0;
    const float* source = (const float*)d_in[0];
    const float* ln_g   = (const float*)d_in[3+o];
    const float* ln_b   = (const float*)d_in[4+o];
    const float* w_gq   = (const float*)d_in[5+o];
    const float* b_gq   = (const float*)d_in[6+o];
    const float* w_kv   = (const float*)d_in[7+o];
    const float* b_kv   = (const float*)d_in[8+o];
    const float* w_o1   = (const float*)d_in[9+o];
    const float* b_o1   = (const float*)d_in[10+o];
    const float* w_o2   = (const float*)d_in[11+o];
    int copies = out_size / (ROWS_T*128);
    if (copies < 1) copies = 1;

    static int attr_done = 0;
    if (!attr_done){
        cudaFuncSetAttribute(proj_fused, cudaFuncAttributeMaxDynamicSharedMemorySize, PROJ_SMEM3);
        cudaFuncSetAttribute(k2a_mt,     cudaFuncAttributeMaxDynamicSharedMemorySize, K2A_SMEM);
        cudaFuncSetAttribute(out_kernel, cudaFuncAttributeMaxDynamicSharedMemorySize, OUT_SMEM3);
        attr_done = 1;
    }

    prep_w<<<192, 256>>>(w_gq, w_kv, w_o1, w_o2);
    proj_fused<<<ROWS_T/128, 256, PROJ_SMEM3>>>(source, ln_g, ln_b, b_gq, b_kv);
    k2a_mt<<<256, 256, K2A_SMEM>>>();
    k2c_reduce<<<dim3(36, 8), 256>>>();
    k2b_qm<<<dim3(74, 4), 256>>>();
    out_kernel<<<ROWS_T/128, 256, OUT_SMEM3>>>(b_o1, source, (float*)d_out, copies);
}

// round 17
// speedup vs baseline: 1.1870x; 1.0151x over previous
#include <cuda_runtime.h>
#include <cuda_bf16.h>
#include <cstdint>

#define ROWS_T 36864
#define SEQ    9216
#define WL     2304
#define SCALE_S (1.0f/1179648.0f)

#define PJ_S32 8704
#define PROJ_SMEM3 ((8704 + 16896)*4)
#define OU_XS3 8704
#define OUT_SMEM3 ((8704 + 8704)*4)
#define KT0 0
#define VT0 1088
#define KT1 2176
#define VT1 3264
#define K2A_SMEM (4352*4)

__device__ unsigned g_gateh[ROWS_T*64];
__device__ unsigned short g_qwh[ROWS_T*128];
__device__ unsigned short g_kwh[ROWS_T*128];
__device__ unsigned short g_vwh[ROWS_T*128];
__device__ unsigned g_wprep[49152];
__device__ unsigned g_Ppart[256*8192];
__device__ float g_ksp[256*128];
__device__ float g_vsp[256*128];
__device__ unsigned g_Mt[36*8192];
__device__ float g_ksum[36*128];
__device__ float g_vsum[36*128];
__device__ unsigned g_atth[ROWS_T*64];

__device__ __forceinline__ float siluf(float x){ return x / (1.0f + __expf(-x)); }

__device__ __forceinline__ int win_from_nat(int r){
    int b = r / SEQ; int p = r - b*SEQ;
    int y = p / 96, x = p - y*96;
    int yr = y + 72; if (yr >= 96) yr -= 96;
    int xr = x + 72; if (xr >= 96) xr -= 96;
    int wy = yr / 48, iy = yr - wy*48;
    int wx = xr / 48, ix = xr - wx*48;
    int w = wy*2 + wx;
    int j;
    if (w == 0)      j = iy*48 + ix;
    else if (w == 1){ int sx = ix >= 24; j = sx*1152 + iy*24 + (ix - sx*24); }
    else if (w == 2){ int sy = iy >= 24; j = sy*1152 + (iy - sy*24)*48 + ix; }
    else { int sy = iy >= 24, sx = ix >= 24;
           j = (sy*2+sx)*576 + (iy - sy*24)*24 + (ix - sx*24); }
    return (b*4 + w)*WL + j;
}
__device__ __forceinline__ int nat_from_reg(int batch, int wv, int wrem){
    int wy = wv >> 1, wx = wv & 1;
    int iy, ix;
    if (wv == 0){ iy = wrem/48; ix = wrem - iy*48; }
    else if (wv == 1){ int sx = wrem >= 1152; int t = wrem - sx*1152; iy = t/24; ix = sx*24 + (t - iy*24); }
    else if (wv == 2){ int sy = wrem >= 1152; int t = wrem - sy*1152; int r = t/48; iy = sy*24 + r; ix = t - r*48; }
    else { int sg = wrem/576; int t = wrem - sg*576; int sy = sg>>1, sx = sg&1;
           int r = t/24; iy = sy*24 + r; ix = sx*24 + (t - r*24); }
    int y = wy*48 + iy + 24; if (y >= 96) y -= 96;
    int x = wx*48 + ix + 24; if (x >= 96) x -= 96;
    return batch*SEQ + y*96 + x;
}

__device__ __forceinline__ uint32_t smem_u32(const void* p){
    uint32_t a;
    asm("{ .reg .u64 t; cvta.to.shared.u64 t, %1; cvt.u32.u64 %0, t; }" : "=r"(a) : "l"(p));
    return a;
}

#define MMA_BF16(c, a0,a1,a2,a3, b0,b1) \
    asm volatile("mma.sync.aligned.m16n8k16.row.col.f32.bf16.bf16.f32 " \
        "{%0,%1,%2,%3},{%4,%5,%6,%7},{%8,%9},{%0,%1,%2,%3};" \
        : "+f"((c)[0]),"+f"((c)[1]),"+f"((c)[2]),"+f"((c)[3]) \
        : "r"(a0),"r"(a1),"r"(a2),"r"(a3),"r"(b0),"r"(b1))

#define LDM_X4(b0,b1,b2,b3,addr) \
    asm volatile("ldmatrix.sync.aligned.m8n8.x4.shared.b16 {%0,%1,%2,%3}, [%4];" \
        : "=r"(b0),"=r"(b1),"=r"(b2),"=r"(b3) : "r"(addr))
#define LDM_X4T(b0,b1,b2,b3,addr) \
    asm volatile("ldmatrix.sync.aligned.m8n8.x4.trans.shared.b16 {%0,%1,%2,%3}, [%4];" \
        : "=r"(b0),"=r"(b1),"=r"(b2),"=r"(b3) : "r"(addr))

#define CP16(dst, src) \
    asm volatile("cp.async.cg.shared.global [%0], [%1], 16;" :: "r"(dst), "l"(src))
#define CP_COMMIT asm volatile("cp.async.commit_group;")
#define CP_WAIT0  asm volatile("cp.async.wait_group 0;")

#define PACK_BF2(u, x, y) do { __nv_bfloat162 _h = __floats2bfloat162_rn((x),(y)); (u) = *(unsigned*)&_h; } while(0)

// ============ K0: weight prep ============
__global__ void prep_w(const float* __restrict__ gq, const float* __restrict__ kv,
                       const float* __restrict__ o1, const float* __restrict__ o2){
    int id = blockIdx.x*256 + threadIdx.x;
    const float* W; int rem, ncols;
    if (id < 32768){ W = (id < 16384) ? gq : kv; ncols = 256; rem = id & 16383; }
    else           { W = (id < 40960) ? o1 : o2; ncols = 128; rem = id & 8191; }
    int n  = rem >> 6;
    int r  = rem & 63;
    int kk = r >> 3, c4 = (r >> 1) & 3, h = r & 1;
    int k0 = kk*16 + h*8 + 2*c4;
    __nv_bfloat162 hh = __floats2bfloat162_rn(W[k0*ncols + n], W[(k0+1)*ncols + n]);
    g_wprep[id] = *(unsigned*)&hh;
}

// ============ K1: fused LN + (gate,Q,K,V) bf16 projection ============
__global__ void __launch_bounds__(256)
proj_fused(const float* __restrict__ src, const float* __restrict__ lg, const float* __restrict__ lb,
           const float* __restrict__ b_gq, const float* __restrict__ b_kv){
    extern __shared__ unsigned smu[];
    float* S32 = (float*)(smu + PJ_S32);
    int tid = threadIdx.x, lane = tid & 31, w = tid >> 5;
    int q = lane >> 2, c4 = lane & 3;
    int wr = w >> 1, wc = w & 1;
    int mbase = blockIdx.x * 128;
    uint32_t smb = smem_u32(smu);

    const float4* Sg = ((const float4*)src) + mbase*32;
    #pragma unroll
    for (int it=0; it<16; it++){
        int idx = tid + it*256; int row = idx>>5, cq = idx&31;
        *(float4*)&S32[row*132 + cq*4] = Sg[idx];
    }
    __syncthreads();
    if (tid < 128){
        float s=0.f, s2=0.f;
        #pragma unroll
        for (int i=0;i<32;i++){
            float4 v = *(float4*)&S32[tid*132 + i*4];
            s += v.x+v.y+v.z+v.w;
            s2 += v.x*v.x+v.y*v.y+v.z*v.z+v.w*v.w;
        }
        float mean = s*(1.f/128.f);
        float var  = s2*(1.f/128.f) - mean*mean;
        float rs   = rsqrtf(var + 1e-5f);
        #pragma unroll
        for (int i=0;i<32;i++){
            float4 v = *(float4*)&S32[tid*132 + i*4];
            float4 g4 = ((const float4*)lg)[i];
            float4 b4 = ((const float4*)lb)[i];
            float x0 = (v.x-mean)*rs*g4.x + b4.x;
            float x1 = (v.y-mean)*rs*g4.y + b4.y;
            float x2 = (v.z-mean)*rs*g4.z + b4.z;
            float x3 = (v.w-mean)*rs*g4.w + b4.w;
            __nv_bfloat162 h0 = __floats2bfloat162_rn(x0, x1);
            __nv_bfloat162 h1 = __floats2bfloat162_rn(x2, x3);
            uint2 u; u.x = *(unsigned*)&h0; u.y = *(unsigned*)&h1;
            *(uint2*)&smu[tid*68 + i*2] = u;
        }
    }
    __syncthreads();

    int lrow = (lane&7) + ((lane>>3)&1)*8;
    int lcolb = ((lane>>4)&1)*16;

    for (int nt=0; nt<4; nt++){
        const unsigned* WB = g_wprep + nt*8192;
        const float* bias  = (nt<2) ? (b_gq + nt*128) : (b_kv + (nt-2)*128);

        float c[2][8][4];
        #pragma unroll
        for (int n=0;n<8;n++){
            int col = wc*64 + n*8 + 2*c4;
            float bb0 = bias[col], bb1 = bias[col+1];
            c[0][n][0]=bb0; c[0][n][1]=bb1; c[0][n][2]=bb0; c[0][n][3]=bb1;
            c[1][n][0]=bb0; c[1][n][1]=bb1; c[1][n][2]=bb0; c[1][n][3]=bb1;
        }
        #pragma unroll
        for (int kk=0;kk<8;kk++){
            unsigned a[2][4];
            #pragma unroll
            for (int mm=0;mm<2;mm++){
                int row = wr*32 + mm*16 + lrow;
                LDM_X4(a[mm][0],a[mm][1],a[mm][2],a[mm][3], smb + row*272 + kk*32 + lcolb);
            }
            #pragma unroll
            for (int n=0;n<8;n++){
                int nabs = wc*64 + n*8 + q;
                uint2 bb = *(const uint2*)(WB + nabs*64 + kk*8 + c4*2);
                MMA_BF16(c[0][n], a[0][0],a[0][1],a[0][2],a[0][3], bb.x, bb.y);
                MMA_BF16(c[1][n], a[1][0],a[1][1],a[1][2],a[1][3], bb.x, bb.y);
            }
        }

        if (nt == 0){
            #pragma unroll
            for (int mm=0;mm<2;mm++){
                int r1 = mbase + wr*32 + q + mm*16;
                #pragma unroll
                for (int n=0;n<8;n++){
                    int ci = wc*32 + n*4 + c4;
                    unsigned u0, u1;
                    PACK_BF2(u0, siluf(c[mm][n][0]), siluf(c[mm][n][1]));
                    PACK_BF2(u1, siluf(c[mm][n][2]), siluf(c[mm][n][3]));
                    g_gateh[r1*64 + ci]     = u0;
                    g_gateh[(r1+8)*64 + ci] = u1;
                }
            }
        } else {
            unsigned short* oh = (nt==1) ? g_qwh : (nt==2 ? g_kwh : g_vwh);
            #pragma unroll
            for (int mm=0;mm<2;mm++){
                int r1 = mbase + wr*32 + q + mm*16;
                int dr1 = win_from_nat(r1);
                int dr2 = win_from_nat(r1+8);
                #pragma unroll
                for (int n=0;n<8;n++){
                    int col = wc*64 + n*8 + 2*c4;
                    __nv_bfloat162 h0 = __floats2bfloat162_rn(siluf(c[mm][n][0]), siluf(c[mm][n][1]));
                    __nv_bfloat162 h1 = __floats2bfloat162_rn(siluf(c[mm][n][2]), siluf(c[mm][n][3]));
                    *(__nv_bfloat162*)(oh + dr1*128 + col) = h0;
                    *(__nv_bfloat162*)(oh + dr2*128 + col) = h1;
                }
            }
        }
    }
}

// ======== K2a: per-chunk partial P, 144-row chunks (grid 256) ========
__global__ void __launch_bounds__(256)
k2a_mt(){
    extern __shared__ unsigned smw[];
    int tid = threadIdx.x, lane = tid & 31, w = tid >> 5;
    int q = lane >> 2, c4 = lane & 3;
    int cid = blockIdx.x;
    int batch = cid >> 6, r = cid & 63;
    int sl, ck;
    if (r < 16){ sl = 0; ck = r; }
    else if (r < 48){ sl = 1 + ((r-16)>>3); ck = (r-16)&7; }
    else { sl = 5 + ((r-48)>>2); ck = (r-48)&3; }
    int win = (sl==0)?0 : (sl<=2?1 : (sl<=4?2:3));
    int off = (sl==0)?0 : (sl==1?0 : (sl==2?1152 : (sl==3?0 : (sl==4?1152 : (sl-5)*576))));
    int grow = (batch*4 + win)*WL + off + ck*144;

    uint32_t smb = smem_u32(smw);
    const uint4* gk4 = (const uint4*)g_kwh;
    const uint4* gv4 = (const uint4*)g_vwh;

    float c[16][4];
    #pragma unroll
    for (int n=0;n<16;n++){ c[n][0]=0.f; c[n][1]=0.f; c[n][2]=0.f; c[n][3]=0.f; }
    float svacc = 0.f;

    uint32_t aOff = ((lane&7) + ((lane>>4)&1)*8)*272u + w*32u + ((lane>>3)&1)*16u;
    uint32_t bOff = ((lane&7) + ((lane>>3)&1)*8)*272u + ((lane>>4)&1)*16u;

    {
        int row = tid >> 4, q16 = tid & 15;
        CP16(smb + (KT0 + row*68 + q16*4)*4, (const void*)(gk4 + (grow + row)*16 + q16));
        CP16(smb + (VT0 + row*68 + q16*4)*4, (const void*)(gv4 + (grow + row)*16 + q16));
        CP_COMMIT;
    }
    CP_WAIT0;
    __syncthreads();

    const unsigned short* sp = (const unsigned short*)smw;

    for (int it=0; it<9; it++){
        int cK = (it&1) ? KT1 : KT0;
        int cV = (it&1) ? VT1 : VT0;
        int nK = (it&1) ? KT0 : KT1;
        int nV = (it&1) ? VT0 : VT1;
        if (it+1 < 9){
            int row = tid >> 4, q16 = tid & 15;
            int gr = grow + (it+1)*16 + row;
            CP16(smb + (nK + row*68 + q16*4)*4, (const void*)(gk4 + gr*16 + q16));
            CP16(smb + (nV + row*68 + q16*4)*4, (const void*)(gv4 + gr*16 + q16));
            CP_COMMIT;
        }
        unsigned a0,a1,a2,a3;
        LDM_X4T(a0,a1,a2,a3, smb + cV*4 + aOff);
        #pragma unroll
        for (int ng2=0; ng2<8; ng2++){
            unsigned b0,b1,b2,b3;
            LDM_X4T(b0,b1,b2,b3, smb + cK*4 + bOff + ng2*32);
            MMA_BF16(c[2*ng2],   a0,a1,a2,a3, b0,b1);
            MMA_BF16(c[2*ng2+1], a0,a1,a2,a3, b2,b3);
        }
        {
            int base = (tid < 128) ? (cK*2 + tid) : (cV*2 + (tid-128));
            #pragma unroll
            for (int rr=0; rr<16; rr++){
                unsigned short hv = sp[base + rr*136];
                svacc += __bfloat162float(*(__nv_bfloat16*)&hv);
            }
        }
        CP_WAIT0;
        __syncthreads();
    }

    unsigned* pb = g_Ppart + cid*8192;
    int d2a = w*16 + q, d2b = d2a + 8;
    #pragma unroll
    for (int ng=0; ng<16; ng++){
        int u = ng*4 + c4;
        PACK_BF2(pb[d2a*64 + u], c[ng][0], c[ng][1]);
        PACK_BF2(pb[d2b*64 + u], c[ng][2], c[ng][3]);
    }
    if (tid < 128) g_ksp[cid*128 + tid] = svacc;
    else           g_vsp[cid*128 + (tid-128)] = svacc;
}

// ======= K2c: reduce bf16 partials -> bf16 frag-ordered Mt (grid 36x16) =======
__global__ void k2c_reduce(){
    int s = blockIdx.x;
    int part = blockIdx.y;              // 0..15
    int batch = s / 9, sl = s - batch*9;
    int cb, nch;
    if (sl == 0){ cb = 0; nch = 16; }
    else if (sl < 5){ cb = 16 + (sl-1)*8; nch = 8; }
    else { cb = 48 + (sl-5)*4; nch = 4; }
    cb += batch*64;
    int tid = threadIdx.x;

    #pragma unroll
    for (int e=0; e<2; e++){
        int idx = part*512 + tid + e*256;
        int n = idx >> 6, f = idx & 63;
        int kk = f >> 3, rr = f & 7;
        int c4v = rr >> 1, h = rr & 1;
        int u = kk*8 + h*4 + c4v;
        float s0 = 0.f, s1 = 0.f;
        #pragma unroll 4
        for (int cc=0; cc<nch; cc++){
            unsigned pv = g_Ppart[(cb+cc)*8192 + n*64 + u];
            __nv_bfloat162 hb = *(__nv_bfloat162*)&pv;
            s0 += __low2float(hb); s1 += __high2float(hb);
        }
        __nv_bfloat162 hh = __floats2bfloat162_rn(s0, s1);
        g_Mt[s*8192 + idx] = *(unsigned*)&hh;
    }
    if (part == 0){
        if (tid < 128){
            float a = 0.f;
            for (int cc=0; cc<nch; cc++) a += g_ksp[(cb+cc)*128 + tid];
            g_ksum[s*128 + tid] = a;
        } else {
            int t = tid - 128;
            float a = 0.f;
            for (int cc=0; cc<nch; cc++) a += g_vsp[(cb+cc)*128 + t];
            g_vsum[s*128 + t] = a;
        }
    }
}

// ============ K2b: O = (vsum + SCALE*Q@Mt)/l * gate, scatter natural bf16 ============
__global__ void __launch_bounds__(256)
k2b_qm(){
    int tid = threadIdx.x, lane = tid & 31, w = tid >> 5;
    int q = lane >> 2, c4 = lane & 3;
    int r0 = w*16 + q;
    int bx = blockIdx.x, batch = blockIdx.y;
    int sl, qt;
    if (bx < 18){ sl = 0; qt = bx; }
    else if (bx < 54){ int e = bx - 18; sl = 1 + e/9; qt = e - (sl-1)*9; }
    else { int e = bx - 54; sl = 5 + e/5; qt = e - (sl-5)*5; }
    int win = (sl==0)?0 : (sl<=2?1 : (sl<=4?2:3));
    int off = (sl==0)?0 : (sl==1?0 : (sl==2?1152 : (sl==3?0 : (sl==4?1152 : (sl-5)*576))));
    int len = (sl==0)?2304 : (sl<5?1152:576);
    int gsb = (batch*4 + win)*WL + off;

    int ra = qt*128 + r0;
    int rb = ra + 8;
    int va = ra < len, vb = rb < len;
    int rac = va ? ra : len-1;
    int rbc = vb ? rb : len-1;

    unsigned aq[8][4];
    {
        const unsigned* qp = (const unsigned*)g_qwh;
        int rA = (gsb + rac)*64, rB = (gsb + rbc)*64;
        #pragma unroll
        for (int kk=0;kk<8;kk++){
            aq[kk][0] = qp[rA + kk*8 + c4];
            aq[kk][1] = qp[rB + kk*8 + c4];
            aq[kk][2] = qp[rA + kk*8 + c4 + 4];
            aq[kk][3] = qp[rB + kk*8 + c4 + 4];
        }
    }

    const unsigned* MtS = g_Mt  + (batch*9 + sl)*8192;
    const float*    ksS = g_ksum + (batch*9 + sl)*128;
    const float*    vsS = g_vsum + (batch*9 + sl)*128;

    float c[16][4];
    #pragma unroll
    for (int n=0;n<16;n++){ c[n][0]=0.f; c[n][1]=0.f; c[n][2]=0.f; c[n][3]=0.f; }
    #pragma unroll
    for (int kk=0;kk<8;kk++){
        #pragma unroll
        for (int ng=0; ng<16; ng++){
            uint2 bb = *(const uint2*)(MtS + (ng*8+q)*64 + kk*8 + c4*2);
            MMA_BF16(c[ng], aq[kk][0],aq[kk][1],aq[kk][2],aq[kk][3], bb.x, bb.y);
        }
    }

    float d0 = 0.f, d1 = 0.f;
    #pragma unroll
    for (int kk=0;kk<8;kk++){
        #pragma unroll
        for (int h=0; h<2; h++){
            float2 ks2 = *(const float2*)(ksS + kk*16 + h*8 + 2*c4);
            unsigned ua = aq[kk][h*2], ub = aq[kk][h*2+1];
            __nv_bfloat162 ha = *(__nv_bfloat162*)&ua;
            __nv_bfloat162 hb = *(__nv_bfloat162*)&ub;
            d0 += __low2float(ha)*ks2.x + __high2float(ha)*ks2.y;
            d1 += __low2float(hb)*ks2.x + __high2float(hb)*ks2.y;
        }
    }
    d0 += __shfl_xor_sync(0xffffffffu, d0, 1);
    d0 += __shfl_xor_sync(0xffffffffu, d0, 2);
    d1 += __shfl_xor_sync(0xffffffffu, d1, 1);
    d1 += __shfl_xor_sync(0xffffffffu, d1, 2);
    float inv0 = __fdividef(1.f, (float)len + SCALE_S*d0);
    float inv1 = __fdividef(1.f, (float)len + SCALE_S*d1);

    int natr0 = va ? nat_from_reg(batch, win, off + ra) : 0;
    int natr1 = vb ? nat_from_reg(batch, win, off + rb) : 0;

    #pragma unroll
    for (int ng=0; ng<16; ng++){
        int col = ng*8 + 2*c4;
        float2 vs2 = *(const float2*)(vsS + col);
        if (va){
            unsigned gu = g_gateh[natr0*64 + ng*4 + c4];
            __nv_bfloat162 gh = *(__nv_bfloat162*)&gu;
            float ox = (vs2.x + SCALE_S*c[ng][0])*inv0*__low2float(gh);
            float oy = (vs2.y + SCALE_S*c[ng][1])*inv0*__high2float(gh);
            __nv_bfloat162 hh = __floats2bfloat162_rn(ox, oy);
            g_atth[natr0*64 + ng*4 + c4] = *(unsigned*)&hh;
        }
        if (vb){
            unsigned gu = g_gateh[natr1*64 + ng*4 + c4];
            __nv_bfloat162 gh = *(__nv_bfloat162*)&gu;
            float ox = (vs2.x + SCALE_S*c[ng][2])*inv1*__low2float(gh);
            float oy = (vs2.y + SCALE_S*c[ng][3])*inv1*__high2float(gh);
            __nv_bfloat162 hh = __floats2bfloat162_rn(ox, oy);
            g_atth[natr1*64 + ng*4 + c4] = *(unsigned*)&hh;
        }
    }
}

// ====== K3: bf16 silu(X@W1+b1)@W2 + residual ======
__global__ void __launch_bounds__(256)
out_kernel(const float* __restrict__ b1, const float* __restrict__ src,
           float* __restrict__ outp, int copies){
    extern __shared__ unsigned smu[];
    unsigned* Ah = smu;
    unsigned* Xs = smu + OU_XS3;
    int tid = threadIdx.x, lane = tid & 31, w = tid >> 5;
    int q = lane >> 2, c4 = lane & 3;
    int wr = w >> 1, wc = w & 1;
    int mbase = blockIdx.x * 128;
    uint32_t smbA = smem_u32(Ah);
    uint32_t smbX = smem_u32(Xs);

    #pragma unroll
    for (int it=0; it<16; it++){
        int idx = tid + it*256; int row = idx>>5, cq = idx&31;
        uint2 v = ((const uint2*)g_atth)[(size_t)(mbase+row)*32 + cq];
        *(uint2*)&Ah[row*68 + cq*2] = v;
    }
    __syncthreads();

    int lrow = (lane&7) + ((lane>>3)&1)*8;
    int lcolb = ((lane>>4)&1)*16;

    const unsigned* WB1 = g_wprep + 32768;
    float c[2][8][4];
    #pragma unroll
    for (int n=0;n<8;n++){
        int col = wc*64 + n*8 + 2*c4;
        float bb0 = b1[col], bb1v = b1[col+1];
        c[0][n][0]=bb0; c[0][n][1]=bb1v; c[0][n][2]=bb0; c[0][n][3]=bb1v;
        c[1][n][0]=bb0; c[1][n][1]=bb1v; c[1][n][2]=bb0; c[1][n][3]=bb1v;
    }
    #pragma unroll
    for (int kk=0;kk<8;kk++){
        unsigned a[2][4];
        #pragma unroll
        for (int mm=0;mm<2;mm++){
            int row = wr*32 + mm*16 + lrow;
            LDM_X4(a[mm][0],a[mm][1],a[mm][2],a[mm][3], smbA + row*272 + kk*32 + lcolb);
        }
        #pragma unroll
        for (int n=0;n<8;n++){
            int nabs = wc*64 + n*8 + q;
            uint2 bb = *(const uint2*)(WB1 + nabs*64 + kk*8 + c4*2);
            MMA_BF16(c[0][n], a[0][0],a[0][1],a[0][2],a[0][3], bb.x, bb.y);
            MMA_BF16(c[1][n], a[1][0],a[1][1],a[1][2],a[1][3], bb.x, bb.y);
        }
    }
    #pragma unroll
    for (int mm=0;mm<2;mm++){
        int r1 = wr*32 + q + mm*16;
        #pragma unroll
        for (int n=0;n<8;n++){
            int ci = wc*32 + n*4 + c4;
            __nv_bfloat162 h0 = __floats2bfloat162_rn(siluf(c[mm][n][0]), siluf(c[mm][n][1]));
            __nv_bfloat162 h1 = __floats2bfloat162_rn(siluf(c[mm][n][2]), siluf(c[mm][n][3]));
            Xs[r1*68 + ci]     = *(unsigned*)&h0;
            Xs[(r1+8)*68 + ci] = *(unsigned*)&h1;
        }
    }
    __syncthreads();

    const unsigned* WB2 = g_wprep + 40960;
    float c2[2][8][4];
    #pragma unroll
    for (int mm=0;mm<2;mm++)
        #pragma unroll
        for (int n=0;n<8;n++){ c2[mm][n][0]=0.f; c2[mm][n][1]=0.f; c2[mm][n][2]=0.f; c2[mm][n][3]=0.f; }
    #pragma unroll
    for (int kk=0;kk<8;kk++){
        unsigned a[2][4];
        #pragma unroll
        for (int mm=0;mm<2;mm++){
            int row = wr*32 + mm*16 + lrow;
            LDM_X4(a[mm][0],a[mm][1],a[mm][2],a[mm][3], smbX + row*272 + kk*32 + lcolb);
        }
        #pragma unroll
        for (int n=0;n<8;n++){
            int nabs = wc*64 + n*8 + q;
            uint2 bb = *(const uint2*)(WB2 + nabs*64 + kk*8 + c4*2);
            MMA_BF16(c2[0][n], a[0][0],a[0][1],a[0][2],a[0][3], bb.x, bb.y);
            MMA_BF16(c2[1][n], a[1][0],a[1][1],a[1][2],a[1][3], bb.x, bb.y);
        }
    }
    #pragma unroll
    for (int mm=0;mm<2;mm++){
        int r1 = mbase + wr*32 + q + mm*16;
        #pragma unroll
        for (int n=0;n<8;n++){
            int col = wc*64 + n*8 + 2*c4;
            float2 s0 = *(const float2*)(src + r1*128 + col);
            float2 s1 = *(const float2*)(src + (r1+8)*128 + col);
            float2 y0 = { c2[mm][n][0] + s0.x, c2[mm][n][1] + s0.y };
            float2 y1 = { c2[mm][n][2] + s1.x, c2[mm][n][3] + s1.y };
            for (int cp=0; cp<copies; cp++){
                *(float2*)(outp + (size_t)cp*ROWS_T*128 + r1*128 + col)     = y0;
                *(float2*)(outp + (size_t)cp*ROWS_T*128 + (r1+8)*128 + col) = y1;
            }
        }
    }
}

extern "C" void kernel_launch(void* const* d_in, const int* in_sizes, int n_in,
                              void* d_out, int out_size){
    int o = (n_in >= 14 && in_sizes[3] == 1) ? 2 : 0;
    const float* source = (const float*)d_in[0];
    const float* ln_g   = (const float*)d_in[3+o];
    const float* ln_b   = (const float*)d_in[4+o];
    const float* w_gq   = (const float*)d_in[5+o];
    const float* b_gq   = (const float*)d_in[6+o];
    const float* w_kv   = (const float*)d_in[7+o];
    const float* b_kv   = (const float*)d_in[8+o];
    const float* w_o1   = (const float*)d_in[9+o];
    const float* b_o1   = (const float*)d_in[10+o];
    const float* w_o2   = (const float*)d_in[11+o];
    int copies = out_size / (ROWS_T*128);
    if (copies < 1) copies = 1;

    static int attr_done = 0;
    if (!attr_done){
        cudaFuncSetAttribute(proj_fused, cudaFuncAttributeMaxDynamicSharedMemorySize, PROJ_SMEM3);
        cudaFuncSetAttribute(k2a_mt,     cudaFuncAttributeMaxDynamicSharedMemorySize, K2A_SMEM);
        cudaFuncSetAttribute(out_kernel, cudaFuncAttributeMaxDynamicSharedMemorySize, OUT_SMEM3);
        attr_done = 1;
    }

    prep_w<<<192, 256>>>(w_gq, w_kv, w_o1, w_o2);
    proj_fused<<<ROWS_T/128, 256, PROJ_SMEM3>>>(source, ln_g, ln_b, b_gq, b_kv);
    k2a_mt<<<256, 256, K2A_SMEM>>>();
    k2c_reduce<<<dim3(36, 16), 256>>>();
    k2b_qm<<<dim3(74, 4), 256>>>();
    out_kernel<<<ROWS_T/128, 256, OUT_SMEM3>>>(b_o1, source, (float*)d_out, copies);
}